// round 9
// baseline (speedup 1.0000x reference)
#include <cuda_runtime.h>
#include <cstdint>

#define BB 32
#define AA 1024
#define DD 128
#define THR2 0.0025f
#define TMR 64   // MLP rows per block

typedef unsigned long long u64;

// Scratch (allocation-free rule: __device__ globals)
__device__ int      g_cnt[BB * AA];          // per-(batch,group) member counts
__device__ uint32_t g_members[BB * AA * 32]; // per-group ORIGINAL member bitmask
__device__ int      g_ng[BB];                // groups per batch

__device__ __forceinline__ float gelu_exact(float x) {
    return 0.5f * x * (1.0f + erff(x * 0.70710678118654752f));
}

// ---------------------------------------------------------------------------
// Kernel 1: FUSED compaction + adjacency + greedy clustering, 1 block/batch.
// Adjacency is built over compacted (valid) agents directly into SMEM in
// TRANSPOSED layout adjT[word][agent] so every later read is lane-consecutive
// (conflict-free). Word-sequential greedy (exact equivalent of the reference
// sequential scan): agent is a starter iff not near any earlier starter;
// asg[j] = rank of the minimum-index starter near j.
// SMEM: adjT 128KB + coords 8KB + cnt 4KB + small = 143,880 B dynamic.
// ---------------------------------------------------------------------------
__global__ __launch_bounds__(1024, 1)
void cluster_kernel(const float* __restrict__ coords, const int* __restrict__ mask,
                    float* __restrict__ out_mask,   // may be null
                    float* __restrict__ out_a2g)    // may be null
{
    extern __shared__ unsigned char sraw[];
    uint32_t* adjT  = (uint32_t*)sraw;                 // [32][1024]
    float2*   scc   = (float2*)(adjT + 32 * 1024);     // 1024 compacted coords
    int*      s_cnt = (int*)(scc + 1024);              // 1024
    uint32_t* svw   = (uint32_t*)(s_cnt + 1024);       // 32 validity words
    uint32_t* sS    = svw + 32;                        // 32 starter bits
    int*      spre  = (int*)(sS + 32);                 // 33 valid prefix
    int*      sSp   = spre + 33;                       // 33 starter prefix
    __shared__ int s_nv, s_ng;

    const int b   = blockIdx.x;
    const int tid = threadIdx.x;
    const int w   = tid >> 5;
    const int l   = tid & 31;

    // prefetch mask + coords (latencies overlap)
    const int    v = (mask[(size_t)b * AA + tid] != 0);
    const float2 c = ((const float2*)coords)[(size_t)b * AA + tid];
    {
        unsigned m = __ballot_sync(0xffffffffu, v);
        if (l == 0) svw[w] = m;
    }
    s_cnt[tid] = 0;
    __syncthreads();
    if (tid < 32) {
        int cc = __popc(svw[tid]);
        int x = cc;
#pragma unroll
        for (int o = 1; o < 32; o <<= 1) {
            int y = __shfl_up_sync(0xffffffffu, x, o);
            if (tid >= o) x += y;
        }
        spre[tid] = x - cc;
        if (tid == 31) s_nv = x;
        sS[tid] = 0;
    }
    __syncthreads();
    const int nv = s_nv;
    const int nw = (nv + 31) >> 5;

    // scatter valid coords to compacted slots
    if (v) {
        int cp = spre[w] + __popc(svw[w] & ((1u << l) - 1));
        scc[cp] = c;
    }
    __syncthreads();

    // ---- build transposed adjacency: adjT[m][a] bit j = near(a, m*32+j) ----
    {
        const u64* scc64 = (const u64*)scc;
        for (int m = 0; m < nw; m++) {
            float2 cj = scc[(m << 5) + l];
            u64 ncj;
            asm("mov.b64 %0, {%1, %2};"
                : "=l"(ncj) : "r"(__float_as_uint(-cj.x)), "r"(__float_as_uint(-cj.y)));
            uint32_t* dstm = adjT + (m << 10);
#pragma unroll 2
            for (int a = w; a < nv; a += 32) {
                u64 ci2 = scc64[a];
                u64 dp, sq;
                asm("add.rn.f32x2 %0, %1, %2;" : "=l"(dp) : "l"(ci2), "l"(ncj));
                asm("mul.rn.f32x2 %0, %1, %2;" : "=l"(sq) : "l"(dp), "l"(dp));
                float lo = __uint_as_float((unsigned)sq);
                float hi = __uint_as_float((unsigned)(sq >> 32));
                // lo + hi == __fadd_rn(__fmul_rn(dx,dx), __fmul_rn(dy,dy)) exactly
                unsigned bm = __ballot_sync(0xffffffffu, (lo + hi) < THR2);
                if (l == 0) dstm[a] = bm;
            }
        }
    }
    __syncthreads();

    // ---- word-sequential greedy on warp 0 (all reads lane-consecutive) ----
    if (w == 0) {
        for (int k = 0; k < nw; k++) {
            const int a = (k << 5) + l;
            const bool exists = (a < nv);
            unsigned blocked = 0;
#pragma unroll 4
            for (int m = 0; m < k; m++)
                blocked |= adjT[(m << 10) + a] & sS[m];
            const unsigned A = adjT[(k << 10) + a];   // intra-word row
            unsigned und = __ballot_sync(0xffffffffu, exists && !blocked);
            unsigned Sw = 0;
            while (und) {                    // uniform loop
                int bb = __ffs(und) - 1;     // lowest undecided = starter
                Sw |= 1u << bb;
                unsigned nearb = __ballot_sync(0xffffffffu, (A >> bb) & 1u);
                und &= ~(nearb | (1u << bb));
            }
            if (l == 0) sS[k] = Sw;
            __syncwarp();
        }
    }
    __syncthreads();

    // starter prefix (rank -> group id)
    if (tid < 32) {
        int cc = __popc(sS[tid]);
        int x = cc;
#pragma unroll
        for (int o = 1; o < 32; o <<= 1) {
            int y = __shfl_up_sync(0xffffffffu, x, o);
            if (tid >= o) x += y;
        }
        sSp[tid] = x - cc;
        if (tid == 31) s_ng = x;
    }
    __syncthreads();

    // asg for ORIGINAL agents: rank of first starter near agent (min index)
    int asg = -1;
    if (v) {
        int cp = spre[w] + __popc(svw[w] & ((1u << l) - 1));
        int cw = cp >> 5;
        for (int m = 0; m <= cw; m++) {
            unsigned m2 = adjT[(m << 10) + cp] & sS[m];
            if (m2) {
                int bit = __ffs(m2) - 1;
                asg = sSp[m] + __popc(sS[m] & ((1u << bit) - 1));
                break;
            }
        }
    }
    const int ng = s_ng;

    // member masks (original space) + counts via per-warp ballots
    for (int g = 0; g < ng; g++) {
        unsigned mw2 = __ballot_sync(0xffffffffu, asg == g);
        if (l == 0) {
            g_members[((size_t)(b * AA + g)) * 32 + w] = mw2;
            if (mw2) atomicAdd(&s_cnt[g], __popc(mw2));
        }
    }
    __syncthreads();

    // emit
    g_cnt[(size_t)b * AA + tid] = s_cnt[tid];
    if (out_a2g)  out_a2g[(size_t)b * AA + tid]  = (float)asg;
    if (out_mask) out_mask[(size_t)b * AA + tid] = (tid < ng) ? 1.0f : 0.0f;
    if (tid == 0) g_ng[b] = ng;
}

// ---------------------------------------------------------------------------
// Kernel 2: fused fill + sparse MLP. Grid 512 windows of 64 group rows.
// Live rows per window derived from g_ng (groups are contiguous per batch).
// Weight staging: coalesced LDG.128 + scalar transposed STS (<=4-way).
// ---------------------------------------------------------------------------
__global__ __launch_bounds__(512, 1)
void mlp_fill_kernel(const float* __restrict__ emb,
                     const float* __restrict__ W1, const float* __restrict__ b1,
                     const float* __restrict__ W2, const float* __restrict__ b2,
                     float* __restrict__ out)
{
    extern __shared__ float sm[];
    float* sW1T = sm;                  // 16384 floats (4096 float4 slots)
    float* sW2T = sm + 16384;          // 16384
    float* sx   = sm + 32768;          // TMR*DD = 8192
    float* gb1s = sm + 40960;          // 128
    int*   srid = (int*)(sm + 41088);  // 64
    int*   scnt = (int*)(sm + 41152);  // 64

    const int tid  = threadIdx.x;
    const int win  = blockIdx.x;
    const int bb   = win >> 4;              // 16 windows per batch
    const int k0   = (win & 15) * TMR;
    const int ng   = g_ng[bb];
    int live = ng - k0;
    if (live > TMR) live = TMR;
    const bool do_mma = (live > 0);
    const int base = win * TMR;             // == bb*AA + k0

    if (tid < DD) gb1s[tid] = gelu_exact(b1[tid]);
    if (tid < TMR) {
        scnt[tid] = g_cnt[base + tid];
        int rc = tid;
        if (rc > live - 1) rc = live - 1;
        if (rc < 0) rc = 0;
        srid[tid] = base + rc;
    }

    // stage transposed weights: coalesced float4 gmem reads, scalar STS to
    // slot(c,g) = c*32 + (g ^ ((c>>2)&7)), component k&3.
    if (do_mma) {
        const float4* W14 = (const float4*)W1;
        const float4* W24 = (const float4*)W2;
#pragma unroll
        for (int it = 0; it < 8; it++) {
            int i  = tid + it * 512;
            int k  = i >> 5;          // source row (k index)
            int c4 = i & 31;          // source float4-column
            float4 v1 = W14[i];
            float4 v2 = W24[i];
            int g = k >> 2, k3 = k & 3;
            int sw = (g ^ (c4 & 7));
            int s0 = (4 * c4 + 0) * 32 + sw;
            int s1 = (4 * c4 + 1) * 32 + sw;
            int s2 = (4 * c4 + 2) * 32 + sw;
            int s3 = (4 * c4 + 3) * 32 + sw;
            sW1T[s0 * 4 + k3] = v1.x;
            sW1T[s1 * 4 + k3] = v1.y;
            sW1T[s2 * 4 + k3] = v1.z;
            sW1T[s3 * 4 + k3] = v1.w;
            sW2T[s0 * 4 + k3] = v2.x;
            sW2T[s1 * 4 + k3] = v2.y;
            sW2T[s2 * 4 + k3] = v2.z;
            sW2T[s3 * 4 + k3] = v2.w;
        }
    }
    __syncthreads();

    // FILL: constant row for empty groups in this block's window
    if (tid < DD) {
        float a0 = b2[tid], a1 = 0.f, a2 = 0.f, a3 = 0.f;
#pragma unroll 4
        for (int k = 0; k < DD; k += 4) {
            a0 = fmaf(gb1s[k + 0], W2[(k + 0) * DD + tid], a0);
            a1 = fmaf(gb1s[k + 1], W2[(k + 1) * DD + tid], a1);
            a2 = fmaf(gb1s[k + 2], W2[(k + 2) * DD + tid], a2);
            a3 = fmaf(gb1s[k + 3], W2[(k + 3) * DD + tid], a3);
        }
        float cf = (a0 + a1) + (a2 + a3);
        for (int r = 0; r < TMR; r++)
            if (scnt[r] == 0) out[(size_t)(base + r) * DD + tid] = cf;
    }
    if (!do_mma) return;

    const int wp   = tid >> 5;
    const int lane = tid & 31;
    const int r0   = wp * 4;        // 4 rows per warp (16 warps * 4 = 64)
    const int c0   = lane * 4;      // 4 cols per lane
    const int swl  = lane & 7;

    // stage x rows r0..r0+3: gather member rows of each group, mean in regs.
    unsigned mw4[4];
    int gr4[4];
#pragma unroll
    for (int rr = 0; rr < 4; rr++) {
        gr4[rr] = srid[r0 + rr];
        mw4[rr] = g_members[(size_t)gr4[rr] * 32 + lane];
    }
#pragma unroll 1
    for (int rr = 0; rr < 4; rr++) {
        const int gr = gr4[rr];
        const unsigned mw = mw4[rr];
        unsigned nz = __ballot_sync(0xffffffffu, mw != 0);
        const float* ebase = emb + (size_t)(gr & ~(AA - 1)) * DD;  // batch base
        float4 a4 = make_float4(0.f, 0.f, 0.f, 0.f);
        while (nz) {
            int w2i = __ffs(nz) - 1;
            nz &= nz - 1u;
            unsigned m = __shfl_sync(0xffffffffu, mw, w2i);
            while (m) {
                int bit = __ffs(m) - 1;
                m &= m - 1u;
                float4 vv = *((const float4*)(ebase + (size_t)((w2i << 5) + bit) * DD) + lane);
                a4.x += vv.x; a4.y += vv.y; a4.z += vv.z; a4.w += vv.w;
            }
        }
        int cc = __reduce_add_sync(0xffffffffu, (int)__popc(mw));
        float inv = 1.0f / (float)(cc > 1 ? cc : 1);
        a4.x *= inv; a4.y *= inv; a4.z *= inv; a4.w *= inv;
        *(float4*)&sx[(r0 + rr) * DD + c0] = a4;
    }
    __syncwarp();   // warp owns its rows; x within-warp visible

    u64 acc[4][4];

    // ================= layer 1 =================
#pragma unroll
    for (int r = 0; r < 4; r++)
#pragma unroll
        for (int cc = 0; cc < 4; cc++) acc[r][cc] = 0ull;

    {
        const ulonglong2* wp4 = (const ulonglong2*)sW1T;
#pragma unroll 4
        for (int g = 0; g < 32; g++) {
            const int gs = g ^ swl;
            ulonglong2 wv0 = wp4[(c0 + 0) * 32 + gs];
            ulonglong2 wv1 = wp4[(c0 + 1) * 32 + gs];
            ulonglong2 wv2 = wp4[(c0 + 2) * 32 + gs];
            ulonglong2 wv3 = wp4[(c0 + 3) * 32 + gs];
#pragma unroll
            for (int r = 0; r < 4; r++) {
                ulonglong2 xv = *(const ulonglong2*)(sx + (r0 + r) * DD + 4 * g);
                asm("fma.rn.f32x2 %0, %1, %2, %0;" : "+l"(acc[r][0]) : "l"(xv.x), "l"(wv0.x));
                asm("fma.rn.f32x2 %0, %1, %2, %0;" : "+l"(acc[r][1]) : "l"(xv.x), "l"(wv1.x));
                asm("fma.rn.f32x2 %0, %1, %2, %0;" : "+l"(acc[r][2]) : "l"(xv.x), "l"(wv2.x));
                asm("fma.rn.f32x2 %0, %1, %2, %0;" : "+l"(acc[r][3]) : "l"(xv.x), "l"(wv3.x));
                asm("fma.rn.f32x2 %0, %1, %2, %0;" : "+l"(acc[r][0]) : "l"(xv.y), "l"(wv0.y));
                asm("fma.rn.f32x2 %0, %1, %2, %0;" : "+l"(acc[r][1]) : "l"(xv.y), "l"(wv1.y));
                asm("fma.rn.f32x2 %0, %1, %2, %0;" : "+l"(acc[r][2]) : "l"(xv.y), "l"(wv2.y));
                asm("fma.rn.f32x2 %0, %1, %2, %0;" : "+l"(acc[r][3]) : "l"(xv.y), "l"(wv3.y));
            }
        }
    }
    // epilogue 1: h = gelu(lo+hi + b1); warp owns its rows -> no barrier
    {
        float4 bv = *(const float4*)&b1[c0];
#pragma unroll
        for (int r = 0; r < 4; r++) {
            float4 h;
            h.x = gelu_exact(__uint_as_float((unsigned)acc[r][0]) + __uint_as_float((unsigned)(acc[r][0] >> 32)) + bv.x);
            h.y = gelu_exact(__uint_as_float((unsigned)acc[r][1]) + __uint_as_float((unsigned)(acc[r][1] >> 32)) + bv.y);
            h.z = gelu_exact(__uint_as_float((unsigned)acc[r][2]) + __uint_as_float((unsigned)(acc[r][2] >> 32)) + bv.z);
            h.w = gelu_exact(__uint_as_float((unsigned)acc[r][3]) + __uint_as_float((unsigned)(acc[r][3] >> 32)) + bv.w);
            *(float4*)&sx[(r0 + r) * DD + c0] = h;
        }
    }
    __syncwarp();

    // ================= layer 2 =================
#pragma unroll
    for (int r = 0; r < 4; r++)
#pragma unroll
        for (int cc = 0; cc < 4; cc++) acc[r][cc] = 0ull;

    {
        const ulonglong2* wp4 = (const ulonglong2*)sW2T;
#pragma unroll 4
        for (int g = 0; g < 32; g++) {
            const int gs = g ^ swl;
            ulonglong2 wv0 = wp4[(c0 + 0) * 32 + gs];
            ulonglong2 wv1 = wp4[(c0 + 1) * 32 + gs];
            ulonglong2 wv2 = wp4[(c0 + 2) * 32 + gs];
            ulonglong2 wv3 = wp4[(c0 + 3) * 32 + gs];
#pragma unroll
            for (int r = 0; r < 4; r++) {
                ulonglong2 xv = *(const ulonglong2*)(sx + (r0 + r) * DD + 4 * g);
                asm("fma.rn.f32x2 %0, %1, %2, %0;" : "+l"(acc[r][0]) : "l"(xv.x), "l"(wv0.x));
                asm("fma.rn.f32x2 %0, %1, %2, %0;" : "+l"(acc[r][1]) : "l"(xv.x), "l"(wv1.x));
                asm("fma.rn.f32x2 %0, %1, %2, %0;" : "+l"(acc[r][2]) : "l"(xv.x), "l"(wv2.x));
                asm("fma.rn.f32x2 %0, %1, %2, %0;" : "+l"(acc[r][3]) : "l"(xv.x), "l"(wv3.x));
                asm("fma.rn.f32x2 %0, %1, %2, %0;" : "+l"(acc[r][0]) : "l"(xv.y), "l"(wv0.y));
                asm("fma.rn.f32x2 %0, %1, %2, %0;" : "+l"(acc[r][1]) : "l"(xv.y), "l"(wv1.y));
                asm("fma.rn.f32x2 %0, %1, %2, %0;" : "+l"(acc[r][2]) : "l"(xv.y), "l"(wv2.y));
                asm("fma.rn.f32x2 %0, %1, %2, %0;" : "+l"(acc[r][3]) : "l"(xv.y), "l"(wv3.y));
            }
        }
    }
    // epilogue 2: out = lo+hi + b2, store live rows
    {
        float4 bv = *(const float4*)&b2[c0];
#pragma unroll
        for (int r = 0; r < 4; r++) {
            if (r0 + r < live) {
                int gr = srid[r0 + r];
                float4 ov;
                ov.x = __uint_as_float((unsigned)acc[r][0]) + __uint_as_float((unsigned)(acc[r][0] >> 32)) + bv.x;
                ov.y = __uint_as_float((unsigned)acc[r][1]) + __uint_as_float((unsigned)(acc[r][1] >> 32)) + bv.y;
                ov.z = __uint_as_float((unsigned)acc[r][2]) + __uint_as_float((unsigned)(acc[r][2] >> 32)) + bv.z;
                ov.w = __uint_as_float((unsigned)acc[r][3]) + __uint_as_float((unsigned)(acc[r][3] >> 32)) + bv.w;
                *(float4*)&out[(size_t)gr * DD + c0] = ov;
            }
        }
    }
}

// ---------------------------------------------------------------------------
extern "C" void kernel_launch(void* const* d_in, const int* in_sizes, int n_in,
                              void* d_out, int out_size)
{
    const float* emb    = (const float*)d_in[0];
    const float* coords = (const float*)d_in[1];
    const int*   mask   = (const int*)d_in[2];
    const float* W1     = (const float*)d_in[3];
    const float* b1     = (const float*)d_in[4];
    const float* W2     = (const float*)d_in[5];
    const float* b2     = (const float*)d_in[6];

    float* out = (float*)d_out;
    const int tok_elems = BB * AA * DD;
    float* out_mask = (out_size >= tok_elems + BB * AA)     ? out + tok_elems           : nullptr;
    float* out_a2g  = (out_size >= tok_elems + 2 * BB * AA) ? out + tok_elems + BB * AA : nullptr;

    const int smem_cluster = 32 * 1024 * 4 + 1024 * 8 + 1024 * 4
                           + 2 * 32 * 4 + 2 * 33 * 4;                          // 143,880
    const int smem_mlp     = (16384 + 16384 + TMR * DD + DD) * 4 + 2 * TMR * 4; // 164,864

    cudaFuncSetAttribute(cluster_kernel,
                         cudaFuncAttributeMaxDynamicSharedMemorySize, smem_cluster);
    cudaFuncSetAttribute(mlp_fill_kernel,
                         cudaFuncAttributeMaxDynamicSharedMemorySize, smem_mlp);

    cluster_kernel<<<BB, 1024, smem_cluster>>>(coords, mask, out_mask, out_a2g);
    mlp_fill_kernel<<<(BB * AA) / TMR, 512, smem_mlp>>>(emb, W1, b1, W2, b2, out);
}

// round 10
// speedup vs baseline: 1.0255x; 1.0255x over previous
#include <cuda_runtime.h>
#include <cstdint>

#define BB 32
#define AA 1024
#define DD 128
#define THR2 0.0025f
#define TMR 128   // MLP rows per block

typedef unsigned long long u64;

// Scratch (allocation-free rule: __device__ globals)
__device__ int      g_cnt[BB * AA];          // per-(batch,group) member counts
__device__ uint32_t g_adj[BB * AA * 32];     // COMPACTED proximity bitmatrix
__device__ uint32_t g_members[BB * AA * 32]; // per-group ORIGINAL member bitmask
__device__ int      g_ng[BB];                // groups per batch

__device__ __forceinline__ float gelu_exact(float x) {
    return 0.5f * x * (1.0f + erff(x * 0.70710678118654752f));
}

// ---------------------------------------------------------------------------
// Kernel 1: COMPACTED adjacency (valid x valid only).  [R8-measured: 10.4us]
// grid (8, BB): block (x,b) computes compacted rows [128x, 128x+128).
// Warp w handles 4 rows; mask+coords prefetched before the compaction dance.
// ---------------------------------------------------------------------------
__global__ __launch_bounds__(1024, 1)
void adjc_kernel(const float* __restrict__ coords, const int* __restrict__ mask)
{
    __shared__ float2   scc[AA];    // compacted coords
    __shared__ uint32_t svw[32];    // validity words
    __shared__ int      spre[33];   // exclusive prefix of valid counts
    __shared__ int      s_nv;

    const int b   = blockIdx.y;
    const int tid = threadIdx.x;
    const int w   = tid >> 5;
    const int l   = tid & 31;

    // prefetch both global reads up front (latencies overlap)
    const int    v = (mask[(size_t)b * AA + tid] != 0);
    const float2 c = ((const float2*)coords)[(size_t)b * AA + tid];
    {
        unsigned m = __ballot_sync(0xffffffffu, v);
        if (l == 0) svw[w] = m;
    }
    __syncthreads();
    if (tid < 32) {
        int cc = __popc(svw[tid]);
        int x = cc;
#pragma unroll
        for (int o = 1; o < 32; o <<= 1) {
            int y = __shfl_up_sync(0xffffffffu, x, o);
            if (tid >= o) x += y;
        }
        spre[tid] = x - cc;
        if (tid == 31) s_nv = x;
    }
    __syncthreads();
    const int nv = s_nv;

    // scatter valid coords to compacted slots (coords already in regs)
    if (v) {
        int cp = spre[w] + __popc(svw[w] & ((1u << l) - 1));
        scc[cp] = c;
    }
    __syncthreads();

    const int row0 = blockIdx.x * 128;
    if (row0 >= nv) return;
    const int nw = (nv + 31) >> 5;

    const int r0 = row0 + (w << 2);   // 4 rows per warp
    bool   h[4];
    float2 ci[4];
#pragma unroll
    for (int r = 0; r < 4; r++) {
        h[r]  = (r0 + r) < nv;
        ci[r] = scc[h[r] ? (r0 + r) : 0];
    }
    uint32_t* dst = g_adj + ((size_t)(b * AA) + r0) * 32;

    for (int word = 0; word < nw; word++) {
        float2 cj = scc[(word << 5) + l];
        unsigned m[4];
#pragma unroll
        for (int r = 0; r < 4; r++) {
            float dx = ci[r].x - cj.x;
            float dy = ci[r].y - cj.y;
            float d2 = __fadd_rn(__fmul_rn(dx, dx), __fmul_rn(dy, dy));
            m[r] = __ballot_sync(0xffffffffu, d2 < THR2);
        }
        if (l == 0) {
#pragma unroll
            for (int r = 0; r < 4; r++)
                if (h[r]) dst[(size_t)r * 32 + word] = m[r];
        }
    }
}

// ---------------------------------------------------------------------------
// Kernel 2: parallel wavefront clustering (32 blocks x 1024 threads).
// [R7-measured config — fastest scan variant so far]
// Equivalence to the sequential greedy scan:
//   starter[i] <=> no earlier valid starter within THR of i
//   asg[j]      =  rank of the minimum-index starter near j (always <= j)
// ---------------------------------------------------------------------------
__global__ __launch_bounds__(1024, 1)
void scan_kernel(const int* __restrict__ mask,
                 float* __restrict__ out_mask,   // may be null
                 float* __restrict__ out_a2g)    // may be null
{
    extern __shared__ unsigned char sraw[];
    uint32_t* adj   = (uint32_t*)sraw;             // AA*32
    int*      s_cnt = (int*)(adj + AA * 32);       // AA
    uint32_t* svw   = (uint32_t*)(s_cnt + AA);     // 32
    uint32_t* sS    = svw + 32;                    // 32 starter bits (compacted)
    uint32_t* sR    = sS + 32;                     // 32 resolved bits (compacted)
    int*      spre  = (int*)(sR + 32);             // 33 valid prefix
    int*      sSp   = spre + 33;                   // 33 starter prefix
    __shared__ int s_nres, s_nv, s_ng;

    const int b   = blockIdx.x;
    const int tid = threadIdx.x;
    const int w   = tid >> 5;
    const int l   = tid & 31;

    const int v = (mask[(size_t)b * AA + tid] != 0);
    {
        unsigned m = __ballot_sync(0xffffffffu, v);
        if (l == 0) svw[w] = m;
    }
    if (tid == 0) s_nres = 0;
    s_cnt[tid] = 0;
    __syncthreads();
    if (tid < 32) {
        int c = __popc(svw[tid]);
        int x = c;
#pragma unroll
        for (int o = 1; o < 32; o <<= 1) {
            int y = __shfl_up_sync(0xffffffffu, x, o);
            if (tid >= o) x += y;
        }
        spre[tid] = x - c;
        if (tid == 31) s_nv = x;
        sS[tid] = 0;
    }
    __syncthreads();
    const int nv = s_nv;

    if (tid < 32) {   // resolved-init: nonexistent compacted slots are resolved
        int rem = nv - (tid << 5);
        unsigned occ = rem >= 32 ? 0xffffffffu : (rem > 0 ? ((1u << rem) - 1) : 0u);
        sR[tid] = ~occ;
    }
    // bulk load compacted adjacency rows [0, nv)
    {
        const uint4* src = (const uint4*)(g_adj + (size_t)b * AA * 32);
        uint4* dst = (uint4*)adj;
        const int tot = nv * 8;
        for (int i = tid; i < tot; i += 1024) dst[i] = src[i];
    }
    __syncthreads();

    // ---- wavefront: thread tid = compacted agent tid (if < nv) ----
    const bool active = (tid < nv);
    const unsigned ebits = (1u << l) - 1;
    unsigned wm = 0;                       // words with earlier neighbors
    if (active) {
        for (int k = 0; k <= w; k++) {
            unsigned a = adj[tid * 32 + k];
            if (k == w) a &= ebits;
            if (a) wm |= 1u << k;
        }
    }
    bool resolved = !active;
    while (true) {
        bool decR = false, decS = false;
        if (!resolved) {
            bool blocked = false, pend = false;
            unsigned t = wm;
            while (t) {
                int k = __ffs(t) - 1;
                t &= t - 1u;
                unsigned a = adj[tid * 32 + k];
                if (k == w) a &= ebits;
                if (a & sS[k]) { blocked = true; break; }
                if (a & ~sR[k]) pend = true;
            }
            if (blocked)      decR = true;
            else if (!pend) { decS = true; decR = true; }
        }
        __syncthreads();   // snapshot reads complete
        unsigned smw = __ballot_sync(0xffffffffu, decS);
        unsigned rmw = __ballot_sync(0xffffffffu, decR);
        if (l == 0 && smw) sS[w] |= smw;
        if (l == 0 && rmw) { sR[w] |= rmw; atomicAdd(&s_nres, __popc(rmw)); }
        if (decR) resolved = true;
        __syncthreads();   // writes visible
        if (s_nres >= nv) break;
    }

    // starter prefix (rank -> group id)
    if (tid < 32) {
        int c = __popc(sS[tid]);
        int x = c;
#pragma unroll
        for (int o = 1; o < 32; o <<= 1) {
            int y = __shfl_up_sync(0xffffffffu, x, o);
            if (tid >= o) x += y;
        }
        sSp[tid] = x - c;
        if (tid == 31) s_ng = x;
    }
    __syncthreads();

    // asg for ORIGINAL agents: rank of first starter in (compacted row & S)
    int asg = -1;
    if (v) {
        int cp = spre[w] + __popc(svw[w] & ebits);
        int cw = cp >> 5;
        for (int k = 0; k <= cw; k++) {
            unsigned m2 = adj[cp * 32 + k] & sS[k];
            if (m2) {
                int bit = __ffs(m2) - 1;
                asg = sSp[k] + __popc(sS[k] & ((1u << bit) - 1));
                break;
            }
        }
    }
    const int ng = s_ng;

    // member masks (original space) + counts via per-warp ballots
    for (int g = 0; g < ng; g++) {
        unsigned mw2 = __ballot_sync(0xffffffffu, asg == g);
        if (l == 0) {
            g_members[((size_t)(b * AA + g)) * 32 + w] = mw2;
            if (mw2) atomicAdd(&s_cnt[g], __popc(mw2));
        }
    }
    __syncthreads();

    // emit
    g_cnt[(size_t)b * AA + tid] = s_cnt[tid];
    if (out_a2g)  out_a2g[(size_t)b * AA + tid]  = (float)asg;
    if (out_mask) out_mask[(size_t)b * AA + tid] = (tid < ng) ? 1.0f : 0.0f;
    if (tid == 0) g_ng[b] = ng;
}

// ---------------------------------------------------------------------------
// Kernel 3: fused fill + sparse MLP. Grid 256 windows of 128 group rows,
// 1024 threads (32 warps x 4 rows) -> 8 warps/SMSP (2x latency hiding vs 512).
// Weight staging = original R5-R8 form (measured-good). TMR=128 halves the
// per-row staging overhead and wave count.
// SMEM: W1T 64KB + W2T 64KB + x/h 64KB + gb1/srid/scnt = 198,144 B dynamic.
// ---------------------------------------------------------------------------
__global__ __launch_bounds__(1024, 1)
void mlp_fill_kernel(const float* __restrict__ emb,
                     const float* __restrict__ W1, const float* __restrict__ b1,
                     const float* __restrict__ W2, const float* __restrict__ b2,
                     float* __restrict__ out)
{
    extern __shared__ float sm[];
    float* sW1T = sm;                  // 16384 floats (4096 float4 slots)
    float* sW2T = sm + 16384;          // 16384
    float* sx   = sm + 32768;          // TMR*DD = 16384
    float* gb1s = sm + 49152;          // 128
    int*   srid = (int*)(sm + 49280);  // 128
    int*   scnt = (int*)(sm + 49408);  // 128

    const int tid  = threadIdx.x;
    const int win  = blockIdx.x;
    const int bb   = win >> 3;              // 8 windows per batch
    const int k0   = (win & 7) * TMR;
    const int ng   = g_ng[bb];
    int live = ng - k0;
    if (live > TMR) live = TMR;
    const bool do_mma = (live > 0);
    const int base = win * TMR;             // == bb*AA + k0

    if (tid < DD) gb1s[tid] = gelu_exact(b1[tid]);
    if (tid < TMR) {
        scnt[tid] = g_cnt[base + tid];
        int rc = tid;
        if (rc > live - 1) rc = live - 1;
        if (rc < 0) rc = 0;
        srid[tid] = base + rc;
    }

    // stage transposed + swizzled weights: slot(c,g) = c*32 + (g ^ ((c>>2)&7))
    if (do_mma) {
        float4* w1t = (float4*)sW1T;
        float4* w2t = (float4*)sW2T;
#pragma unroll
        for (int it = 0; it < 4; it++) {
            int i = tid + it * 1024;
            int c = i & 127, g = i >> 7;
            int slot = c * 32 + (g ^ ((c >> 2) & 7));
            float4 v1, v2;
            v1.x = W1[(4 * g + 0) * DD + c];
            v1.y = W1[(4 * g + 1) * DD + c];
            v1.z = W1[(4 * g + 2) * DD + c];
            v1.w = W1[(4 * g + 3) * DD + c];
            v2.x = W2[(4 * g + 0) * DD + c];
            v2.y = W2[(4 * g + 1) * DD + c];
            v2.z = W2[(4 * g + 2) * DD + c];
            v2.w = W2[(4 * g + 3) * DD + c];
            w1t[slot] = v1;
            w2t[slot] = v2;
        }
    }
    __syncthreads();

    // FILL: constant row for empty groups in this block's window
    if (tid < DD) {
        float a0 = b2[tid], a1 = 0.f, a2 = 0.f, a3 = 0.f;
#pragma unroll 4
        for (int k = 0; k < DD; k += 4) {
            a0 = fmaf(gb1s[k + 0], W2[(k + 0) * DD + tid], a0);
            a1 = fmaf(gb1s[k + 1], W2[(k + 1) * DD + tid], a1);
            a2 = fmaf(gb1s[k + 2], W2[(k + 2) * DD + tid], a2);
            a3 = fmaf(gb1s[k + 3], W2[(k + 3) * DD + tid], a3);
        }
        float cf = (a0 + a1) + (a2 + a3);
        for (int r = 0; r < TMR; r++)
            if (scnt[r] == 0) out[(size_t)(base + r) * DD + tid] = cf;
    }
    if (!do_mma) return;

    const int wp   = tid >> 5;
    const int lane = tid & 31;
    const int r0   = wp * 4;        // 4 rows per warp (32 warps * 4 = 128)
    const int c0   = lane * 4;      // 4 cols per lane
    const int swl  = lane & 7;

    // stage x rows r0..r0+3: gather member rows of each group, mean in regs.
    unsigned mw4[4];
    int gr4[4];
#pragma unroll
    for (int rr = 0; rr < 4; rr++) {
        gr4[rr] = srid[r0 + rr];
        mw4[rr] = g_members[(size_t)gr4[rr] * 32 + lane];
    }
#pragma unroll 1
    for (int rr = 0; rr < 4; rr++) {
        const int gr = gr4[rr];
        const unsigned mw = mw4[rr];
        unsigned nz = __ballot_sync(0xffffffffu, mw != 0);
        const float* ebase = emb + (size_t)(gr & ~(AA - 1)) * DD;  // batch base
        float4 a4 = make_float4(0.f, 0.f, 0.f, 0.f);
        while (nz) {
            int w2i = __ffs(nz) - 1;
            nz &= nz - 1u;
            unsigned m = __shfl_sync(0xffffffffu, mw, w2i);
            while (m) {
                int bit = __ffs(m) - 1;
                m &= m - 1u;
                float4 vv = *((const float4*)(ebase + (size_t)((w2i << 5) + bit) * DD) + lane);
                a4.x += vv.x; a4.y += vv.y; a4.z += vv.z; a4.w += vv.w;
            }
        }
        int cc = __reduce_add_sync(0xffffffffu, (int)__popc(mw));
        float inv = 1.0f / (float)(cc > 1 ? cc : 1);
        a4.x *= inv; a4.y *= inv; a4.z *= inv; a4.w *= inv;
        *(float4*)&sx[(r0 + rr) * DD + c0] = a4;
    }
    __syncwarp();   // warp owns its rows; x within-warp visible

    u64 acc[4][4];

    // ================= layer 1 =================
#pragma unroll
    for (int r = 0; r < 4; r++)
#pragma unroll
        for (int cc = 0; cc < 4; cc++) acc[r][cc] = 0ull;

    {
        const ulonglong2* wp4 = (const ulonglong2*)sW1T;
#pragma unroll 4
        for (int g = 0; g < 32; g++) {
            const int gs = g ^ swl;
            ulonglong2 wv0 = wp4[(c0 + 0) * 32 + gs];
            ulonglong2 wv1 = wp4[(c0 + 1) * 32 + gs];
            ulonglong2 wv2 = wp4[(c0 + 2) * 32 + gs];
            ulonglong2 wv3 = wp4[(c0 + 3) * 32 + gs];
#pragma unroll
            for (int r = 0; r < 4; r++) {
                ulonglong2 xv = *(const ulonglong2*)(sx + (r0 + r) * DD + 4 * g);
                asm("fma.rn.f32x2 %0, %1, %2, %0;" : "+l"(acc[r][0]) : "l"(xv.x), "l"(wv0.x));
                asm("fma.rn.f32x2 %0, %1, %2, %0;" : "+l"(acc[r][1]) : "l"(xv.x), "l"(wv1.x));
                asm("fma.rn.f32x2 %0, %1, %2, %0;" : "+l"(acc[r][2]) : "l"(xv.x), "l"(wv2.x));
                asm("fma.rn.f32x2 %0, %1, %2, %0;" : "+l"(acc[r][3]) : "l"(xv.x), "l"(wv3.x));
                asm("fma.rn.f32x2 %0, %1, %2, %0;" : "+l"(acc[r][0]) : "l"(xv.y), "l"(wv0.y));
                asm("fma.rn.f32x2 %0, %1, %2, %0;" : "+l"(acc[r][1]) : "l"(xv.y), "l"(wv1.y));
                asm("fma.rn.f32x2 %0, %1, %2, %0;" : "+l"(acc[r][2]) : "l"(xv.y), "l"(wv2.y));
                asm("fma.rn.f32x2 %0, %1, %2, %0;" : "+l"(acc[r][3]) : "l"(xv.y), "l"(wv3.y));
            }
        }
    }
    // epilogue 1: h = gelu(lo+hi + b1); warp owns its rows -> no barrier
    {
        float4 bv = *(const float4*)&b1[c0];
#pragma unroll
        for (int r = 0; r < 4; r++) {
            float4 h;
            h.x = gelu_exact(__uint_as_float((unsigned)acc[r][0]) + __uint_as_float((unsigned)(acc[r][0] >> 32)) + bv.x);
            h.y = gelu_exact(__uint_as_float((unsigned)acc[r][1]) + __uint_as_float((unsigned)(acc[r][1] >> 32)) + bv.y);
            h.z = gelu_exact(__uint_as_float((unsigned)acc[r][2]) + __uint_as_float((unsigned)(acc[r][2] >> 32)) + bv.z);
            h.w = gelu_exact(__uint_as_float((unsigned)acc[r][3]) + __uint_as_float((unsigned)(acc[r][3] >> 32)) + bv.w);
            *(float4*)&sx[(r0 + r) * DD + c0] = h;
        }
    }
    __syncwarp();

    // ================= layer 2 =================
#pragma unroll
    for (int r = 0; r < 4; r++)
#pragma unroll
        for (int cc = 0; cc < 4; cc++) acc[r][cc] = 0ull;

    {
        const ulonglong2* wp4 = (const ulonglong2*)sW2T;
#pragma unroll 4
        for (int g = 0; g < 32; g++) {
            const int gs = g ^ swl;
            ulonglong2 wv0 = wp4[(c0 + 0) * 32 + gs];
            ulonglong2 wv1 = wp4[(c0 + 1) * 32 + gs];
            ulonglong2 wv2 = wp4[(c0 + 2) * 32 + gs];
            ulonglong2 wv3 = wp4[(c0 + 3) * 32 + gs];
#pragma unroll
            for (int r = 0; r < 4; r++) {
                ulonglong2 xv = *(const ulonglong2*)(sx + (r0 + r) * DD + 4 * g);
                asm("fma.rn.f32x2 %0, %1, %2, %0;" : "+l"(acc[r][0]) : "l"(xv.x), "l"(wv0.x));
                asm("fma.rn.f32x2 %0, %1, %2, %0;" : "+l"(acc[r][1]) : "l"(xv.x), "l"(wv1.x));
                asm("fma.rn.f32x2 %0, %1, %2, %0;" : "+l"(acc[r][2]) : "l"(xv.x), "l"(wv2.x));
                asm("fma.rn.f32x2 %0, %1, %2, %0;" : "+l"(acc[r][3]) : "l"(xv.x), "l"(wv3.x));
                asm("fma.rn.f32x2 %0, %1, %2, %0;" : "+l"(acc[r][0]) : "l"(xv.y), "l"(wv0.y));
                asm("fma.rn.f32x2 %0, %1, %2, %0;" : "+l"(acc[r][1]) : "l"(xv.y), "l"(wv1.y));
                asm("fma.rn.f32x2 %0, %1, %2, %0;" : "+l"(acc[r][2]) : "l"(xv.y), "l"(wv2.y));
                asm("fma.rn.f32x2 %0, %1, %2, %0;" : "+l"(acc[r][3]) : "l"(xv.y), "l"(wv3.y));
            }
        }
    }
    // epilogue 2: out = lo+hi + b2, store live rows
    {
        float4 bv = *(const float4*)&b2[c0];
#pragma unroll
        for (int r = 0; r < 4; r++) {
            if (r0 + r < live) {
                int gr = srid[r0 + r];
                float4 ov;
                ov.x = __uint_as_float((unsigned)acc[r][0]) + __uint_as_float((unsigned)(acc[r][0] >> 32)) + bv.x;
                ov.y = __uint_as_float((unsigned)acc[r][1]) + __uint_as_float((unsigned)(acc[r][1] >> 32)) + bv.y;
                ov.z = __uint_as_float((unsigned)acc[r][2]) + __uint_as_float((unsigned)(acc[r][2] >> 32)) + bv.z;
                ov.w = __uint_as_float((unsigned)acc[r][3]) + __uint_as_float((unsigned)(acc[r][3] >> 32)) + bv.w;
                *(float4*)&out[(size_t)gr * DD + c0] = ov;
            }
        }
    }
}

// ---------------------------------------------------------------------------
extern "C" void kernel_launch(void* const* d_in, const int* in_sizes, int n_in,
                              void* d_out, int out_size)
{
    const float* emb    = (const float*)d_in[0];
    const float* coords = (const float*)d_in[1];
    const int*   mask   = (const int*)d_in[2];
    const float* W1     = (const float*)d_in[3];
    const float* b1     = (const float*)d_in[4];
    const float* W2     = (const float*)d_in[5];
    const float* b2     = (const float*)d_in[6];

    float* out = (float*)d_out;
    const int tok_elems = BB * AA * DD;
    float* out_mask = (out_size >= tok_elems + BB * AA)     ? out + tok_elems           : nullptr;
    float* out_a2g  = (out_size >= tok_elems + 2 * BB * AA) ? out + tok_elems + BB * AA : nullptr;

    const int smem_scan = AA * 32 * 4 + AA * 4 + 3 * 32 * 4 + 2 * 33 * 4;      // 135,816
    const int smem_mlp  = (16384 + 16384 + TMR * DD + DD) * 4 + 2 * TMR * 4;   // 198,144

    cudaFuncSetAttribute(scan_kernel,
                         cudaFuncAttributeMaxDynamicSharedMemorySize, smem_scan);
    cudaFuncSetAttribute(mlp_fill_kernel,
                         cudaFuncAttributeMaxDynamicSharedMemorySize, smem_mlp);

    adjc_kernel<<<dim3(8, BB), 1024>>>(coords, mask);
    scan_kernel<<<BB, 1024, smem_scan>>>(mask, out_mask, out_a2g);
    mlp_fill_kernel<<<(BB * AA) / TMR, 1024, smem_mlp>>>(emb, W1, b1, W2, b2, out);
}

// round 11
// speedup vs baseline: 1.1747x; 1.1455x over previous
#include <cuda_runtime.h>
#include <cstdint>

#define BB 32
#define AA 1024
#define DD 128
#define THR2 0.0025f
#define TMR 64   // MLP rows per block

typedef unsigned long long u64;

// Scratch (allocation-free rule: __device__ globals)
__device__ int      g_cnt[BB * AA];          // per-(batch,group) member counts
__device__ uint32_t g_adj[BB * AA * 32];     // COMPACTED proximity bitmatrix
__device__ uint32_t g_members[BB * AA * 32]; // per-group ORIGINAL member bitmask
__device__ int      g_ng[BB];                // groups per batch

__device__ __forceinline__ float gelu_exact(float x) {
    return 0.5f * x * (1.0f + erff(x * 0.70710678118654752f));
}

// ---------------------------------------------------------------------------
// Kernel 1: COMPACTED adjacency (valid x valid only).  [measured 10.3us]
// grid (8, BB): block (x,b) computes compacted rows [128x, 128x+128).
// ---------------------------------------------------------------------------
__global__ __launch_bounds__(1024, 1)
void adjc_kernel(const float* __restrict__ coords, const int* __restrict__ mask)
{
    __shared__ float2   scc[AA];    // compacted coords
    __shared__ uint32_t svw[32];    // validity words
    __shared__ int      spre[33];   // exclusive prefix of valid counts
    __shared__ int      s_nv;

    const int b   = blockIdx.y;
    const int tid = threadIdx.x;
    const int w   = tid >> 5;
    const int l   = tid & 31;

    // prefetch both global reads up front (latencies overlap)
    const int    v = (mask[(size_t)b * AA + tid] != 0);
    const float2 c = ((const float2*)coords)[(size_t)b * AA + tid];
    {
        unsigned m = __ballot_sync(0xffffffffu, v);
        if (l == 0) svw[w] = m;
    }
    __syncthreads();
    if (tid < 32) {
        int cc = __popc(svw[tid]);
        int x = cc;
#pragma unroll
        for (int o = 1; o < 32; o <<= 1) {
            int y = __shfl_up_sync(0xffffffffu, x, o);
            if (tid >= o) x += y;
        }
        spre[tid] = x - cc;
        if (tid == 31) s_nv = x;
    }
    __syncthreads();
    const int nv = s_nv;

    // scatter valid coords to compacted slots (coords already in regs)
    if (v) {
        int cp = spre[w] + __popc(svw[w] & ((1u << l) - 1));
        scc[cp] = c;
    }
    __syncthreads();

    const int row0 = blockIdx.x * 128;
    if (row0 >= nv) return;
    const int nw = (nv + 31) >> 5;

    const int r0 = row0 + (w << 2);   // 4 rows per warp
    bool   h[4];
    float2 ci[4];
#pragma unroll
    for (int r = 0; r < 4; r++) {
        h[r]  = (r0 + r) < nv;
        ci[r] = scc[h[r] ? (r0 + r) : 0];
    }
    uint32_t* dst = g_adj + ((size_t)(b * AA) + r0) * 32;

    for (int word = 0; word < nw; word++) {
        float2 cj = scc[(word << 5) + l];
        unsigned m[4];
#pragma unroll
        for (int r = 0; r < 4; r++) {
            float dx = ci[r].x - cj.x;
            float dy = ci[r].y - cj.y;
            float d2 = __fadd_rn(__fmul_rn(dx, dx), __fmul_rn(dy, dy));
            m[r] = __ballot_sync(0xffffffffu, d2 < THR2);
        }
        if (l == 0) {
#pragma unroll
            for (int r = 0; r < 4; r++)
                if (h[r]) dst[(size_t)r * 32 + word] = m[r];
        }
    }
}

// ---------------------------------------------------------------------------
// Kernel 2: parallel wavefront clustering (32 blocks x 1024 threads).
// [R7-measured — fastest scan variant]
// ---------------------------------------------------------------------------
__global__ __launch_bounds__(1024, 1)
void scan_kernel(const int* __restrict__ mask,
                 float* __restrict__ out_mask,   // may be null
                 float* __restrict__ out_a2g)    // may be null
{
    extern __shared__ unsigned char sraw[];
    uint32_t* adj   = (uint32_t*)sraw;             // AA*32
    int*      s_cnt = (int*)(adj + AA * 32);       // AA
    uint32_t* svw   = (uint32_t*)(s_cnt + AA);     // 32
    uint32_t* sS    = svw + 32;                    // 32 starter bits (compacted)
    uint32_t* sR    = sS + 32;                     // 32 resolved bits (compacted)
    int*      spre  = (int*)(sR + 32);             // 33 valid prefix
    int*      sSp   = spre + 33;                   // 33 starter prefix
    __shared__ int s_nres, s_nv, s_ng;

    const int b   = blockIdx.x;
    const int tid = threadIdx.x;
    const int w   = tid >> 5;
    const int l   = tid & 31;

    const int v = (mask[(size_t)b * AA + tid] != 0);
    {
        unsigned m = __ballot_sync(0xffffffffu, v);
        if (l == 0) svw[w] = m;
    }
    if (tid == 0) s_nres = 0;
    s_cnt[tid] = 0;
    __syncthreads();
    if (tid < 32) {
        int c = __popc(svw[tid]);
        int x = c;
#pragma unroll
        for (int o = 1; o < 32; o <<= 1) {
            int y = __shfl_up_sync(0xffffffffu, x, o);
            if (tid >= o) x += y;
        }
        spre[tid] = x - c;
        if (tid == 31) s_nv = x;
        sS[tid] = 0;
    }
    __syncthreads();
    const int nv = s_nv;

    if (tid < 32) {   // resolved-init: nonexistent compacted slots are resolved
        int rem = nv - (tid << 5);
        unsigned occ = rem >= 32 ? 0xffffffffu : (rem > 0 ? ((1u << rem) - 1) : 0u);
        sR[tid] = ~occ;
    }
    // bulk load compacted adjacency rows [0, nv)
    {
        const uint4* src = (const uint4*)(g_adj + (size_t)b * AA * 32);
        uint4* dst = (uint4*)adj;
        const int tot = nv * 8;
        for (int i = tid; i < tot; i += 1024) dst[i] = src[i];
    }
    __syncthreads();

    // ---- wavefront: thread tid = compacted agent tid (if < nv) ----
    const bool active = (tid < nv);
    const unsigned ebits = (1u << l) - 1;
    unsigned wm = 0;                       // words with earlier neighbors
    if (active) {
        for (int k = 0; k <= w; k++) {
            unsigned a = adj[tid * 32 + k];
            if (k == w) a &= ebits;
            if (a) wm |= 1u << k;
        }
    }
    bool resolved = !active;
    while (true) {
        bool decR = false, decS = false;
        if (!resolved) {
            bool blocked = false, pend = false;
            unsigned t = wm;
            while (t) {
                int k = __ffs(t) - 1;
                t &= t - 1u;
                unsigned a = adj[tid * 32 + k];
                if (k == w) a &= ebits;
                if (a & sS[k]) { blocked = true; break; }
                if (a & ~sR[k]) pend = true;
            }
            if (blocked)      decR = true;
            else if (!pend) { decS = true; decR = true; }
        }
        __syncthreads();   // snapshot reads complete
        unsigned smw = __ballot_sync(0xffffffffu, decS);
        unsigned rmw = __ballot_sync(0xffffffffu, decR);
        if (l == 0 && smw) sS[w] |= smw;
        if (l == 0 && rmw) { sR[w] |= rmw; atomicAdd(&s_nres, __popc(rmw)); }
        if (decR) resolved = true;
        __syncthreads();   // writes visible
        if (s_nres >= nv) break;
    }

    // starter prefix (rank -> group id)
    if (tid < 32) {
        int c = __popc(sS[tid]);
        int x = c;
#pragma unroll
        for (int o = 1; o < 32; o <<= 1) {
            int y = __shfl_up_sync(0xffffffffu, x, o);
            if (tid >= o) x += y;
        }
        sSp[tid] = x - c;
        if (tid == 31) s_ng = x;
    }
    __syncthreads();

    // asg for ORIGINAL agents: rank of first starter in (compacted row & S)
    int asg = -1;
    if (v) {
        int cp = spre[w] + __popc(svw[w] & ebits);
        int cw = cp >> 5;
        for (int k = 0; k <= cw; k++) {
            unsigned m2 = adj[cp * 32 + k] & sS[k];
            if (m2) {
                int bit = __ffs(m2) - 1;
                asg = sSp[k] + __popc(sS[k] & ((1u << bit) - 1));
                break;
            }
        }
    }
    const int ng = s_ng;

    // member masks (original space) + counts via per-warp ballots
    for (int g = 0; g < ng; g++) {
        unsigned mw2 = __ballot_sync(0xffffffffu, asg == g);
        if (l == 0) {
            g_members[((size_t)(b * AA + g)) * 32 + w] = mw2;
            if (mw2) atomicAdd(&s_cnt[g], __popc(mw2));
        }
    }
    __syncthreads();

    // emit
    g_cnt[(size_t)b * AA + tid] = s_cnt[tid];
    if (out_a2g)  out_a2g[(size_t)b * AA + tid]  = (float)asg;
    if (out_mask) out_mask[(size_t)b * AA + tid] = (tid < ng) ? 1.0f : 0.0f;
    if (tid == 0) g_ng[b] = ng;
}

// ---------------------------------------------------------------------------
// Kernel 3: fused fill + sparse MLP. [R7 config: 512 thr, TMR=64]
// ONE change vs R7: staging thread->(c,g) mapping gives lanes c = 4*lane+j so
// (c>>2)&7 = lane&7 -> STS.128 conflict-free (was 4-way bank conflicted).
// ---------------------------------------------------------------------------
__global__ __launch_bounds__(512, 1)
void mlp_fill_kernel(const float* __restrict__ emb,
                     const float* __restrict__ W1, const float* __restrict__ b1,
                     const float* __restrict__ W2, const float* __restrict__ b2,
                     float* __restrict__ out)
{
    extern __shared__ float sm[];
    float* sW1T = sm;                  // 16384 floats (4096 float4 slots)
    float* sW2T = sm + 16384;          // 16384
    float* sx   = sm + 32768;          // TMR*DD = 8192
    float* gb1s = sm + 40960;          // 128
    int*   srid = (int*)(sm + 41088);  // 64
    int*   scnt = (int*)(sm + 41152);  // 64

    const int tid  = threadIdx.x;
    const int win  = blockIdx.x;
    const int bb   = win >> 4;              // 16 windows per batch
    const int k0   = (win & 15) * TMR;
    const int ng   = g_ng[bb];
    int live = ng - k0;
    if (live > TMR) live = TMR;
    const bool do_mma = (live > 0);
    const int base = win * TMR;             // == bb*AA + k0

    if (tid < DD) gb1s[tid] = gelu_exact(b1[tid]);
    if (tid < TMR) {
        scnt[tid] = g_cnt[base + tid];
        int rc = tid;
        if (rc > live - 1) rc = live - 1;
        if (rc < 0) rc = 0;
        srid[tid] = base + rc;
    }

    // stage transposed + swizzled weights: slot(c,g) = c*32 + (g ^ ((c>>2)&7))
    // thread mapping c = 4*(i%32) + ((i>>5)&3): lanes -> c = 4*lane+j, so
    // stores have (c>>2)&7 = lane&7 (distinct per octet) -> conflict-free.
    if (do_mma) {
        float4* w1t = (float4*)sW1T;
        float4* w2t = (float4*)sW2T;
#pragma unroll
        for (int it = 0; it < 8; it++) {
            int i = tid + it * 512;
            int c = ((i & 31) << 2) | ((i >> 5) & 3);
            int g = i >> 7;
            int slot = c * 32 + (g ^ ((c >> 2) & 7));
            float4 v1, v2;
            v1.x = W1[(4 * g + 0) * DD + c];
            v1.y = W1[(4 * g + 1) * DD + c];
            v1.z = W1[(4 * g + 2) * DD + c];
            v1.w = W1[(4 * g + 3) * DD + c];
            v2.x = W2[(4 * g + 0) * DD + c];
            v2.y = W2[(4 * g + 1) * DD + c];
            v2.z = W2[(4 * g + 2) * DD + c];
            v2.w = W2[(4 * g + 3) * DD + c];
            w1t[slot] = v1;
            w2t[slot] = v2;
        }
    }
    __syncthreads();

    // FILL: constant row for empty groups in this block's window
    if (tid < DD) {
        float a0 = b2[tid], a1 = 0.f, a2 = 0.f, a3 = 0.f;
#pragma unroll 4
        for (int k = 0; k < DD; k += 4) {
            a0 = fmaf(gb1s[k + 0], W2[(k + 0) * DD + tid], a0);
            a1 = fmaf(gb1s[k + 1], W2[(k + 1) * DD + tid], a1);
            a2 = fmaf(gb1s[k + 2], W2[(k + 2) * DD + tid], a2);
            a3 = fmaf(gb1s[k + 3], W2[(k + 3) * DD + tid], a3);
        }
        float cf = (a0 + a1) + (a2 + a3);
        for (int r = 0; r < TMR; r++)
            if (scnt[r] == 0) out[(size_t)(base + r) * DD + tid] = cf;
    }
    if (!do_mma) return;

    const int wp   = tid >> 5;
    const int lane = tid & 31;
    const int r0   = wp * 4;        // 4 rows per warp (16 warps * 4 = 64)
    const int c0   = lane * 4;      // 4 cols per lane
    const int swl  = lane & 7;

    // stage x rows r0..r0+3: gather member rows of each group, mean in regs.
    unsigned mw4[4];
    int gr4[4];
#pragma unroll
    for (int rr = 0; rr < 4; rr++) {
        gr4[rr] = srid[r0 + rr];
        mw4[rr] = g_members[(size_t)gr4[rr] * 32 + lane];
    }
#pragma unroll 1
    for (int rr = 0; rr < 4; rr++) {
        const int gr = gr4[rr];
        const unsigned mw = mw4[rr];
        unsigned nz = __ballot_sync(0xffffffffu, mw != 0);
        const float* ebase = emb + (size_t)(gr & ~(AA - 1)) * DD;  // batch base
        float4 a4 = make_float4(0.f, 0.f, 0.f, 0.f);
        while (nz) {
            int w2i = __ffs(nz) - 1;
            nz &= nz - 1u;
            unsigned m = __shfl_sync(0xffffffffu, mw, w2i);
            while (m) {
                int bit = __ffs(m) - 1;
                m &= m - 1u;
                float4 vv = *((const float4*)(ebase + (size_t)((w2i << 5) + bit) * DD) + lane);
                a4.x += vv.x; a4.y += vv.y; a4.z += vv.z; a4.w += vv.w;
            }
        }
        int cc = __reduce_add_sync(0xffffffffu, (int)__popc(mw));
        float inv = 1.0f / (float)(cc > 1 ? cc : 1);
        a4.x *= inv; a4.y *= inv; a4.z *= inv; a4.w *= inv;
        *(float4*)&sx[(r0 + rr) * DD + c0] = a4;
    }
    __syncwarp();   // warp owns its rows; x within-warp visible

    u64 acc[4][4];

    // ================= layer 1 =================
#pragma unroll
    for (int r = 0; r < 4; r++)
#pragma unroll
        for (int cc = 0; cc < 4; cc++) acc[r][cc] = 0ull;

    {
        const ulonglong2* wp4 = (const ulonglong2*)sW1T;
#pragma unroll 4
        for (int g = 0; g < 32; g++) {
            const int gs = g ^ swl;
            ulonglong2 wv0 = wp4[(c0 + 0) * 32 + gs];
            ulonglong2 wv1 = wp4[(c0 + 1) * 32 + gs];
            ulonglong2 wv2 = wp4[(c0 + 2) * 32 + gs];
            ulonglong2 wv3 = wp4[(c0 + 3) * 32 + gs];
#pragma unroll
            for (int r = 0; r < 4; r++) {
                ulonglong2 xv = *(const ulonglong2*)(sx + (r0 + r) * DD + 4 * g);
                asm("fma.rn.f32x2 %0, %1, %2, %0;" : "+l"(acc[r][0]) : "l"(xv.x), "l"(wv0.x));
                asm("fma.rn.f32x2 %0, %1, %2, %0;" : "+l"(acc[r][1]) : "l"(xv.x), "l"(wv1.x));
                asm("fma.rn.f32x2 %0, %1, %2, %0;" : "+l"(acc[r][2]) : "l"(xv.x), "l"(wv2.x));
                asm("fma.rn.f32x2 %0, %1, %2, %0;" : "+l"(acc[r][3]) : "l"(xv.x), "l"(wv3.x));
                asm("fma.rn.f32x2 %0, %1, %2, %0;" : "+l"(acc[r][0]) : "l"(xv.y), "l"(wv0.y));
                asm("fma.rn.f32x2 %0, %1, %2, %0;" : "+l"(acc[r][1]) : "l"(xv.y), "l"(wv1.y));
                asm("fma.rn.f32x2 %0, %1, %2, %0;" : "+l"(acc[r][2]) : "l"(xv.y), "l"(wv2.y));
                asm("fma.rn.f32x2 %0, %1, %2, %0;" : "+l"(acc[r][3]) : "l"(xv.y), "l"(wv3.y));
            }
        }
    }
    // epilogue 1: h = gelu(lo+hi + b1); warp owns its rows -> no barrier
    {
        float4 bv = *(const float4*)&b1[c0];
#pragma unroll
        for (int r = 0; r < 4; r++) {
            float4 h;
            h.x = gelu_exact(__uint_as_float((unsigned)acc[r][0]) + __uint_as_float((unsigned)(acc[r][0] >> 32)) + bv.x);
            h.y = gelu_exact(__uint_as_float((unsigned)acc[r][1]) + __uint_as_float((unsigned)(acc[r][1] >> 32)) + bv.y);
            h.z = gelu_exact(__uint_as_float((unsigned)acc[r][2]) + __uint_as_float((unsigned)(acc[r][2] >> 32)) + bv.z);
            h.w = gelu_exact(__uint_as_float((unsigned)acc[r][3]) + __uint_as_float((unsigned)(acc[r][3] >> 32)) + bv.w);
            *(float4*)&sx[(r0 + r) * DD + c0] = h;
        }
    }
    __syncwarp();

    // ================= layer 2 =================
#pragma unroll
    for (int r = 0; r < 4; r++)
#pragma unroll
        for (int cc = 0; cc < 4; cc++) acc[r][cc] = 0ull;

    {
        const ulonglong2* wp4 = (const ulonglong2*)sW2T;
#pragma unroll 4
        for (int g = 0; g < 32; g++) {
            const int gs = g ^ swl;
            ulonglong2 wv0 = wp4[(c0 + 0) * 32 + gs];
            ulonglong2 wv1 = wp4[(c0 + 1) * 32 + gs];
            ulonglong2 wv2 = wp4[(c0 + 2) * 32 + gs];
            ulonglong2 wv3 = wp4[(c0 + 3) * 32 + gs];
#pragma unroll
            for (int r = 0; r < 4; r++) {
                ulonglong2 xv = *(const ulonglong2*)(sx + (r0 + r) * DD + 4 * g);
                asm("fma.rn.f32x2 %0, %1, %2, %0;" : "+l"(acc[r][0]) : "l"(xv.x), "l"(wv0.x));
                asm("fma.rn.f32x2 %0, %1, %2, %0;" : "+l"(acc[r][1]) : "l"(xv.x), "l"(wv1.x));
                asm("fma.rn.f32x2 %0, %1, %2, %0;" : "+l"(acc[r][2]) : "l"(xv.x), "l"(wv2.x));
                asm("fma.rn.f32x2 %0, %1, %2, %0;" : "+l"(acc[r][3]) : "l"(xv.x), "l"(wv3.x));
                asm("fma.rn.f32x2 %0, %1, %2, %0;" : "+l"(acc[r][0]) : "l"(xv.y), "l"(wv0.y));
                asm("fma.rn.f32x2 %0, %1, %2, %0;" : "+l"(acc[r][1]) : "l"(xv.y), "l"(wv1.y));
                asm("fma.rn.f32x2 %0, %1, %2, %0;" : "+l"(acc[r][2]) : "l"(xv.y), "l"(wv2.y));
                asm("fma.rn.f32x2 %0, %1, %2, %0;" : "+l"(acc[r][3]) : "l"(xv.y), "l"(wv3.y));
            }
        }
    }
    // epilogue 2: out = lo+hi + b2, store live rows
    {
        float4 bv = *(const float4*)&b2[c0];
#pragma unroll
        for (int r = 0; r < 4; r++) {
            if (r0 + r < live) {
                int gr = srid[r0 + r];
                float4 ov;
                ov.x = __uint_as_float((unsigned)acc[r][0]) + __uint_as_float((unsigned)(acc[r][0] >> 32)) + bv.x;
                ov.y = __uint_as_float((unsigned)acc[r][1]) + __uint_as_float((unsigned)(acc[r][1] >> 32)) + bv.y;
                ov.z = __uint_as_float((unsigned)acc[r][2]) + __uint_as_float((unsigned)(acc[r][2] >> 32)) + bv.z;
                ov.w = __uint_as_float((unsigned)acc[r][3]) + __uint_as_float((unsigned)(acc[r][3] >> 32)) + bv.w;
                *(float4*)&out[(size_t)gr * DD + c0] = ov;
            }
        }
    }
}

// ---------------------------------------------------------------------------
extern "C" void kernel_launch(void* const* d_in, const int* in_sizes, int n_in,
                              void* d_out, int out_size)
{
    const float* emb    = (const float*)d_in[0];
    const float* coords = (const float*)d_in[1];
    const int*   mask   = (const int*)d_in[2];
    const float* W1     = (const float*)d_in[3];
    const float* b1     = (const float*)d_in[4];
    const float* W2     = (const float*)d_in[5];
    const float* b2     = (const float*)d_in[6];

    float* out = (float*)d_out;
    const int tok_elems = BB * AA * DD;
    float* out_mask = (out_size >= tok_elems + BB * AA)     ? out + tok_elems           : nullptr;
    float* out_a2g  = (out_size >= tok_elems + 2 * BB * AA) ? out + tok_elems + BB * AA : nullptr;

    const int smem_scan = AA * 32 * 4 + AA * 4 + 3 * 32 * 4 + 2 * 33 * 4;      // 135,816
    const int smem_mlp  = (16384 + 16384 + TMR * DD + DD) * 4 + 2 * TMR * 4;   // 164,864

    cudaFuncSetAttribute(scan_kernel,
                         cudaFuncAttributeMaxDynamicSharedMemorySize, smem_scan);
    cudaFuncSetAttribute(mlp_fill_kernel,
                         cudaFuncAttributeMaxDynamicSharedMemorySize, smem_mlp);

    adjc_kernel<<<dim3(8, BB), 1024>>>(coords, mask);
    scan_kernel<<<BB, 1024, smem_scan>>>(mask, out_mask, out_a2g);
    mlp_fill_kernel<<<(BB * AA) / TMR, 512, smem_mlp>>>(emb, W1, b1, W2, b2, out);
}

// round 12
// speedup vs baseline: 1.2470x; 1.0615x over previous
#include <cuda_runtime.h>
#include <cstdint>

#define BB 32
#define AA 1024
#define DD 128
#define THR2 0.0025f
#define TMR 64   // MLP rows per block

typedef unsigned long long u64;

// Scratch (allocation-free rule: __device__ globals)
__device__ int      g_cnt[BB * AA];          // per-(batch,group) member counts
__device__ uint32_t g_adj[BB * AA * 32];     // COMPACTED proximity bitmatrix
__device__ int      g_goff[BB * AA];         // per-(batch,group) member-list offset
__device__ int      g_memlist[BB * AA + 8];  // agents counting-sorted by (batch,group); +8 pad for safe overread
__device__ int      g_ng[BB];                // groups per batch

__device__ __forceinline__ float gelu_exact(float x) {
    return 0.5f * x * (1.0f + erff(x * 0.70710678118654752f));
}

// ---------------------------------------------------------------------------
// Kernel 1: COMPACTED adjacency (valid x valid only).  [measured 10.0us]
// grid (8, BB): block (x,b) computes compacted rows [128x, 128x+128).
// ---------------------------------------------------------------------------
__global__ __launch_bounds__(1024, 1)
void adjc_kernel(const float* __restrict__ coords, const int* __restrict__ mask)
{
    __shared__ float2   scc[AA];    // compacted coords
    __shared__ uint32_t svw[32];    // validity words
    __shared__ int      spre[33];   // exclusive prefix of valid counts
    __shared__ int      s_nv;

    const int b   = blockIdx.y;
    const int tid = threadIdx.x;
    const int w   = tid >> 5;
    const int l   = tid & 31;

    // prefetch both global reads up front (latencies overlap)
    const int    v = (mask[(size_t)b * AA + tid] != 0);
    const float2 c = ((const float2*)coords)[(size_t)b * AA + tid];
    {
        unsigned m = __ballot_sync(0xffffffffu, v);
        if (l == 0) svw[w] = m;
    }
    __syncthreads();
    if (tid < 32) {
        int cc = __popc(svw[tid]);
        int x = cc;
#pragma unroll
        for (int o = 1; o < 32; o <<= 1) {
            int y = __shfl_up_sync(0xffffffffu, x, o);
            if (tid >= o) x += y;
        }
        spre[tid] = x - cc;
        if (tid == 31) s_nv = x;
    }
    __syncthreads();
    const int nv = s_nv;

    // scatter valid coords to compacted slots (coords already in regs)
    if (v) {
        int cp = spre[w] + __popc(svw[w] & ((1u << l) - 1));
        scc[cp] = c;
    }
    __syncthreads();

    const int row0 = blockIdx.x * 128;
    if (row0 >= nv) return;
    const int nw = (nv + 31) >> 5;

    const int r0 = row0 + (w << 2);   // 4 rows per warp
    bool   h[4];
    float2 ci[4];
#pragma unroll
    for (int r = 0; r < 4; r++) {
        h[r]  = (r0 + r) < nv;
        ci[r] = scc[h[r] ? (r0 + r) : 0];
    }
    uint32_t* dst = g_adj + ((size_t)(b * AA) + r0) * 32;

    for (int word = 0; word < nw; word++) {
        float2 cj = scc[(word << 5) + l];
        unsigned m[4];
#pragma unroll
        for (int r = 0; r < 4; r++) {
            float dx = ci[r].x - cj.x;
            float dy = ci[r].y - cj.y;
            float d2 = __fadd_rn(__fmul_rn(dx, dx), __fmul_rn(dy, dy));
            m[r] = __ballot_sync(0xffffffffu, d2 < THR2);
        }
        if (l == 0) {
#pragma unroll
            for (int r = 0; r < 4; r++)
                if (h[r]) dst[(size_t)r * 32 + word] = m[r];
        }
    }
}

// ---------------------------------------------------------------------------
// Kernel 2: parallel wavefront clustering (32 blocks x 1024 threads).
// [R7-measured core] + NEW: emits counting-sorted member list per batch
// (deterministic: rank = #earlier members, via member-mask popc; offsets via
// block prefix-sum; member masks staged in the then-dead adj smem region).
// ---------------------------------------------------------------------------
__global__ __launch_bounds__(1024, 1)
void scan_kernel(const int* __restrict__ mask,
                 float* __restrict__ out_mask,   // may be null
                 float* __restrict__ out_a2g)    // may be null
{
    extern __shared__ unsigned char sraw[];
    uint32_t* adj    = (uint32_t*)sraw;             // AA*32
    int*      s_cnt  = (int*)(adj + AA * 32);       // AA
    int*      s_goff = s_cnt + AA;                  // AA
    uint32_t* svw    = (uint32_t*)(s_goff + AA);    // 32
    uint32_t* sS     = svw + 32;                    // 32 starter bits (compacted)
    uint32_t* sR     = sS + 32;                     // 32 resolved bits (compacted)
    int*      spre   = (int*)(sR + 32);             // 33 valid prefix
    int*      sSp    = spre + 33;                   // 33 starter prefix
    int*      s_wtot = sSp + 33;                    // 32 warp totals
    __shared__ int s_nres, s_nv, s_ng;

    const int b   = blockIdx.x;
    const int tid = threadIdx.x;
    const int w   = tid >> 5;
    const int l   = tid & 31;

    const int v = (mask[(size_t)b * AA + tid] != 0);
    {
        unsigned m = __ballot_sync(0xffffffffu, v);
        if (l == 0) svw[w] = m;
    }
    if (tid == 0) s_nres = 0;
    s_cnt[tid] = 0;
    __syncthreads();
    if (tid < 32) {
        int c = __popc(svw[tid]);
        int x = c;
#pragma unroll
        for (int o = 1; o < 32; o <<= 1) {
            int y = __shfl_up_sync(0xffffffffu, x, o);
            if (tid >= o) x += y;
        }
        spre[tid] = x - c;
        if (tid == 31) s_nv = x;
        sS[tid] = 0;
    }
    __syncthreads();
    const int nv = s_nv;

    if (tid < 32) {   // resolved-init: nonexistent compacted slots are resolved
        int rem = nv - (tid << 5);
        unsigned occ = rem >= 32 ? 0xffffffffu : (rem > 0 ? ((1u << rem) - 1) : 0u);
        sR[tid] = ~occ;
    }
    // bulk load compacted adjacency rows [0, nv)
    {
        const uint4* src = (const uint4*)(g_adj + (size_t)b * AA * 32);
        uint4* dst = (uint4*)adj;
        const int tot = nv * 8;
        for (int i = tid; i < tot; i += 1024) dst[i] = src[i];
    }
    __syncthreads();

    // ---- wavefront: thread tid = compacted agent tid (if < nv) ----
    const bool active = (tid < nv);
    const unsigned ebits = (1u << l) - 1;
    unsigned wm = 0;                       // words with earlier neighbors
    if (active) {
        for (int k = 0; k <= w; k++) {
            unsigned a = adj[tid * 32 + k];
            if (k == w) a &= ebits;
            if (a) wm |= 1u << k;
        }
    }
    bool resolved = !active;
    while (true) {
        bool decR = false, decS = false;
        if (!resolved) {
            bool blocked = false, pend = false;
            unsigned t = wm;
            while (t) {
                int k = __ffs(t) - 1;
                t &= t - 1u;
                unsigned a = adj[tid * 32 + k];
                if (k == w) a &= ebits;
                if (a & sS[k]) { blocked = true; break; }
                if (a & ~sR[k]) pend = true;
            }
            if (blocked)      decR = true;
            else if (!pend) { decS = true; decR = true; }
        }
        __syncthreads();   // snapshot reads complete
        unsigned smw = __ballot_sync(0xffffffffu, decS);
        unsigned rmw = __ballot_sync(0xffffffffu, decR);
        if (l == 0 && smw) sS[w] |= smw;
        if (l == 0 && rmw) { sR[w] |= rmw; atomicAdd(&s_nres, __popc(rmw)); }
        if (decR) resolved = true;
        __syncthreads();   // writes visible
        if (s_nres >= nv) break;
    }

    // starter prefix (rank -> group id)
    if (tid < 32) {
        int c = __popc(sS[tid]);
        int x = c;
#pragma unroll
        for (int o = 1; o < 32; o <<= 1) {
            int y = __shfl_up_sync(0xffffffffu, x, o);
            if (tid >= o) x += y;
        }
        sSp[tid] = x - c;
        if (tid == 31) s_ng = x;
    }
    __syncthreads();

    // asg for ORIGINAL agents: rank of first starter in (compacted row & S)
    int asg = -1;
    if (v) {
        int cp = spre[w] + __popc(svw[w] & ebits);
        int cw = cp >> 5;
        for (int k = 0; k <= cw; k++) {
            unsigned m2 = adj[cp * 32 + k] & sS[k];
            if (m2) {
                int bit = __ffs(m2) - 1;
                asg = sSp[k] + __popc(sS[k] & ((1u << bit) - 1));
                break;
            }
        }
    }
    const int ng = s_ng;

    // ---- member masks into dead adj smem + counts ----
    __syncthreads();                 // all adj reads done; reuse as sMemb
    uint32_t* sMemb = adj;           // sMemb[g*32+w] = members of g in warp w
    for (int g = 0; g < ng; g++) {
        unsigned mw2 = __ballot_sync(0xffffffffu, asg == g);
        if (l == 0) {
            sMemb[g * 32 + w] = mw2;
            if (mw2) atomicAdd(&s_cnt[g], __popc(mw2));
        }
    }
    __syncthreads();

    // ---- exclusive prefix of counts -> s_goff ----
    {
        int val = s_cnt[tid];
        int x = val;
#pragma unroll
        for (int o = 1; o < 32; o <<= 1) {
            int y = __shfl_up_sync(0xffffffffu, x, o);
            if (l >= o) x += y;
        }
        if (l == 31) s_wtot[w] = x;
        __syncthreads();
        if (tid < 32) {
            int c = s_wtot[tid];
            int y = c;
#pragma unroll
            for (int o = 1; o < 32; o <<= 1) {
                int z = __shfl_up_sync(0xffffffffu, y, o);
                if (tid >= o) y += z;
            }
            s_wtot[tid] = y - c;    // exclusive warp offsets
        }
        __syncthreads();
        s_goff[tid] = x - val + s_wtot[w];
    }
    __syncthreads();

    // ---- counting-sorted member list (ascending agent order per group) ----
    if (v) {
        int g = asg;
        int rank = __popc(sMemb[g * 32 + w] & ebits);
        for (int ww = 0; ww < w; ww++) rank += __popc(sMemb[g * 32 + ww]);
        g_memlist[b * AA + s_goff[g] + rank] = tid;
    }

    // emit
    g_cnt[(size_t)b * AA + tid]  = s_cnt[tid];
    g_goff[(size_t)b * AA + tid] = s_goff[tid];
    if (out_a2g)  out_a2g[(size_t)b * AA + tid]  = (float)asg;
    if (out_mask) out_mask[(size_t)b * AA + tid] = (tid < ng) ? 1.0f : 0.0f;
    if (tid == 0) g_ng[b] = ng;
}

// ---------------------------------------------------------------------------
// Kernel 3: fused fill + sparse MLP. [R11 config: 512 thr, TMR=64]
// Gather now walks the contiguous member list: 4 independent LDG.128 per
// chunk (MLP>=4), zero ballots/shfls — the old per-member serial dependency
// chain (ballot->shfl->LDG->FADD, ~600cyc each) is gone.
// ---------------------------------------------------------------------------
__global__ __launch_bounds__(512, 1)
void mlp_fill_kernel(const float* __restrict__ emb,
                     const float* __restrict__ W1, const float* __restrict__ b1,
                     const float* __restrict__ W2, const float* __restrict__ b2,
                     float* __restrict__ out)
{
    extern __shared__ float sm[];
    float* sW1T = sm;                  // 16384 floats (4096 float4 slots)
    float* sW2T = sm + 16384;          // 16384
    float* sx   = sm + 32768;          // TMR*DD = 8192
    float* gb1s = sm + 40960;          // 128
    int*   srid = (int*)(sm + 41088);  // 64
    int*   scnt = (int*)(sm + 41152);  // 64

    const int tid  = threadIdx.x;
    const int win  = blockIdx.x;
    const int bb   = win >> 4;              // 16 windows per batch
    const int k0   = (win & 15) * TMR;
    const int ng   = g_ng[bb];
    int live = ng - k0;
    if (live > TMR) live = TMR;
    const bool do_mma = (live > 0);
    const int base = win * TMR;             // == bb*AA + k0

    if (tid < DD) gb1s[tid] = gelu_exact(b1[tid]);
    if (tid < TMR) {
        scnt[tid] = g_cnt[base + tid];
        int rc = tid;
        if (rc > live - 1) rc = live - 1;
        if (rc < 0) rc = 0;
        srid[tid] = base + rc;
    }

    // stage transposed + swizzled weights: slot(c,g) = c*32 + (g ^ ((c>>2)&7))
    // thread mapping c = 4*(i%32) + ((i>>5)&3): conflict-free STS.128.
    if (do_mma) {
        float4* w1t = (float4*)sW1T;
        float4* w2t = (float4*)sW2T;
#pragma unroll
        for (int it = 0; it < 8; it++) {
            int i = tid + it * 512;
            int c = ((i & 31) << 2) | ((i >> 5) & 3);
            int g = i >> 7;
            int slot = c * 32 + (g ^ ((c >> 2) & 7));
            float4 v1, v2;
            v1.x = W1[(4 * g + 0) * DD + c];
            v1.y = W1[(4 * g + 1) * DD + c];
            v1.z = W1[(4 * g + 2) * DD + c];
            v1.w = W1[(4 * g + 3) * DD + c];
            v2.x = W2[(4 * g + 0) * DD + c];
            v2.y = W2[(4 * g + 1) * DD + c];
            v2.z = W2[(4 * g + 2) * DD + c];
            v2.w = W2[(4 * g + 3) * DD + c];
            w1t[slot] = v1;
            w2t[slot] = v2;
        }
    }
    __syncthreads();

    // FILL: constant row for empty groups in this block's window
    if (tid < DD) {
        float a0 = b2[tid], a1 = 0.f, a2 = 0.f, a3 = 0.f;
#pragma unroll 4
        for (int k = 0; k < DD; k += 4) {
            a0 = fmaf(gb1s[k + 0], W2[(k + 0) * DD + tid], a0);
            a1 = fmaf(gb1s[k + 1], W2[(k + 1) * DD + tid], a1);
            a2 = fmaf(gb1s[k + 2], W2[(k + 2) * DD + tid], a2);
            a3 = fmaf(gb1s[k + 3], W2[(k + 3) * DD + tid], a3);
        }
        float cf = (a0 + a1) + (a2 + a3);
        for (int r = 0; r < TMR; r++)
            if (scnt[r] == 0) out[(size_t)(base + r) * DD + tid] = cf;
    }
    if (!do_mma) return;

    const int wp   = tid >> 5;
    const int lane = tid & 31;
    const int r0   = wp * 4;        // 4 rows per warp (16 warps * 4 = 64)
    const int c0   = lane * 4;      // 4 cols per lane
    const int swl  = lane & 7;

    // stage x rows r0..r0+3: mean over contiguous member list.
    int gr4[4], cnt4[4], off4[4];
#pragma unroll
    for (int rr = 0; rr < 4; rr++) {
        gr4[rr]  = srid[r0 + rr];
        cnt4[rr] = scnt[gr4[rr] - base];
        off4[rr] = g_goff[gr4[rr]];        // 4 independent LDGs (overlap)
    }
    const float* ebase = emb + (size_t)bb * AA * DD;
    const int*   mlb   = g_memlist + (size_t)bb * AA;
#pragma unroll 1
    for (int rr = 0; rr < 4; rr++) {
        const int cnt = cnt4[rr];
        const int* ml = mlb + off4[rr];
        float4 a4 = make_float4(0.f, 0.f, 0.f, 0.f);
        int j = 0;
        for (; j + 4 <= cnt; j += 4) {
            int i0 = ml[j], i1 = ml[j + 1], i2 = ml[j + 2], i3 = ml[j + 3];
            float4 v0 = *((const float4*)(ebase + (size_t)i0 * DD) + lane);
            float4 v1 = *((const float4*)(ebase + (size_t)i1 * DD) + lane);
            float4 v2 = *((const float4*)(ebase + (size_t)i2 * DD) + lane);
            float4 v3 = *((const float4*)(ebase + (size_t)i3 * DD) + lane);
            a4.x += (v0.x + v1.x) + (v2.x + v3.x);
            a4.y += (v0.y + v1.y) + (v2.y + v3.y);
            a4.z += (v0.z + v1.z) + (v2.z + v3.z);
            a4.w += (v0.w + v1.w) + (v2.w + v3.w);
        }
        int rem = cnt - j;
        if (rem > 0) {
            // overreads hit g_memlist pad / other entries: values always in
            // [0, AA) (zero-init or written tids), so the row loads are safe;
            // contributions gated by f1/f2.
            int i0 = ml[j], i1 = ml[j + 1], i2 = ml[j + 2];
            float f1 = rem > 1 ? 1.f : 0.f;
            float f2 = rem > 2 ? 1.f : 0.f;
            float4 v0 = *((const float4*)(ebase + (size_t)i0 * DD) + lane);
            float4 v1 = *((const float4*)(ebase + (size_t)i1 * DD) + lane);
            float4 v2 = *((const float4*)(ebase + (size_t)i2 * DD) + lane);
            a4.x += v0.x + f1 * v1.x + f2 * v2.x;
            a4.y += v0.y + f1 * v1.y + f2 * v2.y;
            a4.z += v0.z + f1 * v1.z + f2 * v2.z;
            a4.w += v0.w + f1 * v1.w + f2 * v2.w;
        }
        float inv = 1.0f / (float)(cnt > 1 ? cnt : 1);
        a4.x *= inv; a4.y *= inv; a4.z *= inv; a4.w *= inv;
        *(float4*)&sx[(r0 + rr) * DD + c0] = a4;
    }
    __syncwarp();   // warp owns its rows; x within-warp visible

    u64 acc[4][4];

    // ================= layer 1 =================
#pragma unroll
    for (int r = 0; r < 4; r++)
#pragma unroll
        for (int cc = 0; cc < 4; cc++) acc[r][cc] = 0ull;

    {
        const ulonglong2* wp4 = (const ulonglong2*)sW1T;
#pragma unroll 4
        for (int g = 0; g < 32; g++) {
            const int gs = g ^ swl;
            ulonglong2 wv0 = wp4[(c0 + 0) * 32 + gs];
            ulonglong2 wv1 = wp4[(c0 + 1) * 32 + gs];
            ulonglong2 wv2 = wp4[(c0 + 2) * 32 + gs];
            ulonglong2 wv3 = wp4[(c0 + 3) * 32 + gs];
#pragma unroll
            for (int r = 0; r < 4; r++) {
                ulonglong2 xv = *(const ulonglong2*)(sx + (r0 + r) * DD + 4 * g);
                asm("fma.rn.f32x2 %0, %1, %2, %0;" : "+l"(acc[r][0]) : "l"(xv.x), "l"(wv0.x));
                asm("fma.rn.f32x2 %0, %1, %2, %0;" : "+l"(acc[r][1]) : "l"(xv.x), "l"(wv1.x));
                asm("fma.rn.f32x2 %0, %1, %2, %0;" : "+l"(acc[r][2]) : "l"(xv.x), "l"(wv2.x));
                asm("fma.rn.f32x2 %0, %1, %2, %0;" : "+l"(acc[r][3]) : "l"(xv.x), "l"(wv3.x));
                asm("fma.rn.f32x2 %0, %1, %2, %0;" : "+l"(acc[r][0]) : "l"(xv.y), "l"(wv0.y));
                asm("fma.rn.f32x2 %0, %1, %2, %0;" : "+l"(acc[r][1]) : "l"(xv.y), "l"(wv1.y));
                asm("fma.rn.f32x2 %0, %1, %2, %0;" : "+l"(acc[r][2]) : "l"(xv.y), "l"(wv2.y));
                asm("fma.rn.f32x2 %0, %1, %2, %0;" : "+l"(acc[r][3]) : "l"(xv.y), "l"(wv3.y));
            }
        }
    }
    // epilogue 1: h = gelu(lo+hi + b1); warp owns its rows -> no barrier
    {
        float4 bv = *(const float4*)&b1[c0];
#pragma unroll
        for (int r = 0; r < 4; r++) {
            float4 h;
            h.x = gelu_exact(__uint_as_float((unsigned)acc[r][0]) + __uint_as_float((unsigned)(acc[r][0] >> 32)) + bv.x);
            h.y = gelu_exact(__uint_as_float((unsigned)acc[r][1]) + __uint_as_float((unsigned)(acc[r][1] >> 32)) + bv.y);
            h.z = gelu_exact(__uint_as_float((unsigned)acc[r][2]) + __uint_as_float((unsigned)(acc[r][2] >> 32)) + bv.z);
            h.w = gelu_exact(__uint_as_float((unsigned)acc[r][3]) + __uint_as_float((unsigned)(acc[r][3] >> 32)) + bv.w);
            *(float4*)&sx[(r0 + r) * DD + c0] = h;
        }
    }
    __syncwarp();

    // ================= layer 2 =================
#pragma unroll
    for (int r = 0; r < 4; r++)
#pragma unroll
        for (int cc = 0; cc < 4; cc++) acc[r][cc] = 0ull;

    {
        const ulonglong2* wp4 = (const ulonglong2*)sW2T;
#pragma unroll 4
        for (int g = 0; g < 32; g++) {
            const int gs = g ^ swl;
            ulonglong2 wv0 = wp4[(c0 + 0) * 32 + gs];
            ulonglong2 wv1 = wp4[(c0 + 1) * 32 + gs];
            ulonglong2 wv2 = wp4[(c0 + 2) * 32 + gs];
            ulonglong2 wv3 = wp4[(c0 + 3) * 32 + gs];
#pragma unroll
            for (int r = 0; r < 4; r++) {
                ulonglong2 xv = *(const ulonglong2*)(sx + (r0 + r) * DD + 4 * g);
                asm("fma.rn.f32x2 %0, %1, %2, %0;" : "+l"(acc[r][0]) : "l"(xv.x), "l"(wv0.x));
                asm("fma.rn.f32x2 %0, %1, %2, %0;" : "+l"(acc[r][1]) : "l"(xv.x), "l"(wv1.x));
                asm("fma.rn.f32x2 %0, %1, %2, %0;" : "+l"(acc[r][2]) : "l"(xv.x), "l"(wv2.x));
                asm("fma.rn.f32x2 %0, %1, %2, %0;" : "+l"(acc[r][3]) : "l"(xv.x), "l"(wv3.x));
                asm("fma.rn.f32x2 %0, %1, %2, %0;" : "+l"(acc[r][0]) : "l"(xv.y), "l"(wv0.y));
                asm("fma.rn.f32x2 %0, %1, %2, %0;" : "+l"(acc[r][1]) : "l"(xv.y), "l"(wv1.y));
                asm("fma.rn.f32x2 %0, %1, %2, %0;" : "+l"(acc[r][2]) : "l"(xv.y), "l"(wv2.y));
                asm("fma.rn.f32x2 %0, %1, %2, %0;" : "+l"(acc[r][3]) : "l"(xv.y), "l"(wv3.y));
            }
        }
    }
    // epilogue 2: out = lo+hi + b2, store live rows
    {
        float4 bv = *(const float4*)&b2[c0];
#pragma unroll
        for (int r = 0; r < 4; r++) {
            if (r0 + r < live) {
                int gr = srid[r0 + r];
                float4 ov;
                ov.x = __uint_as_float((unsigned)acc[r][0]) + __uint_as_float((unsigned)(acc[r][0] >> 32)) + bv.x;
                ov.y = __uint_as_float((unsigned)acc[r][1]) + __uint_as_float((unsigned)(acc[r][1] >> 32)) + bv.y;
                ov.z = __uint_as_float((unsigned)acc[r][2]) + __uint_as_float((unsigned)(acc[r][2] >> 32)) + bv.z;
                ov.w = __uint_as_float((unsigned)acc[r][3]) + __uint_as_float((unsigned)(acc[r][3] >> 32)) + bv.w;
                *(float4*)&out[(size_t)gr * DD + c0] = ov;
            }
        }
    }
}

// ---------------------------------------------------------------------------
extern "C" void kernel_launch(void* const* d_in, const int* in_sizes, int n_in,
                              void* d_out, int out_size)
{
    const float* emb    = (const float*)d_in[0];
    const float* coords = (const float*)d_in[1];
    const int*   mask   = (const int*)d_in[2];
    const float* W1     = (const float*)d_in[3];
    const float* b1     = (const float*)d_in[4];
    const float* W2     = (const float*)d_in[5];
    const float* b2     = (const float*)d_in[6];

    float* out = (float*)d_out;
    const int tok_elems = BB * AA * DD;
    float* out_mask = (out_size >= tok_elems + BB * AA)     ? out + tok_elems           : nullptr;
    float* out_a2g  = (out_size >= tok_elems + 2 * BB * AA) ? out + tok_elems + BB * AA : nullptr;

    const int smem_scan = AA * 32 * 4 + 2 * AA * 4 + 3 * 32 * 4 + 2 * 33 * 4 + 32 * 4; // ~139,912
    const int smem_mlp  = (16384 + 16384 + TMR * DD + DD) * 4 + 2 * TMR * 4;           // 164,864

    cudaFuncSetAttribute(scan_kernel,
                         cudaFuncAttributeMaxDynamicSharedMemorySize, smem_scan);
    cudaFuncSetAttribute(mlp_fill_kernel,
                         cudaFuncAttributeMaxDynamicSharedMemorySize, smem_mlp);

    adjc_kernel<<<dim3(8, BB), 1024>>>(coords, mask);
    scan_kernel<<<BB, 1024, smem_scan>>>(mask, out_mask, out_a2g);
    mlp_fill_kernel<<<(BB * AA) / TMR, 512, smem_mlp>>>(emb, W1, b1, W2, b2, out);
}

// round 13
// speedup vs baseline: 1.5355x; 1.2314x over previous
#include <cuda_runtime.h>
#include <cstdint>

#define BB 32
#define AA 1024
#define DD 128
#define THR2 0.0025f
#define TMR 64   // MLP rows per block

typedef unsigned long long u64;

// Scratch (allocation-free rule: __device__ globals)
__device__ int      g_cnt[BB * AA];          // per-(batch,group) member counts
__device__ uint32_t g_adj[BB * AA * 32];     // COMPACTED proximity bitmatrix
__device__ int      g_goff[BB * AA];         // per-(batch,group) member-list offset
__device__ int      g_memlist[BB * AA + 8];  // agents counting-sorted by (batch,group); +8 pad for safe overread
__device__ int      g_ng[BB];                // groups per batch

__device__ __forceinline__ float gelu_exact(float x) {
    return 0.5f * x * (1.0f + erff(x * 0.70710678118654752f));
}

// ---------------------------------------------------------------------------
// Kernel 1: COMPACTED adjacency (valid x valid only).
// grid (8, BB): block (x,b) computes compacted rows [128x, 128x+128).
// Distance via packed f32x2 (sign-XOR negation): lane arithmetic exactly
// equals __fadd_rn(__fmul_rn(dx,dx), __fmul_rn(dy,dy)).
// ---------------------------------------------------------------------------
__global__ __launch_bounds__(1024, 1)
void adjc_kernel(const float* __restrict__ coords, const int* __restrict__ mask)
{
    __shared__ float2   scc[AA];    // compacted coords
    __shared__ uint32_t svw[32];    // validity words
    __shared__ int      spre[33];   // exclusive prefix of valid counts
    __shared__ int      s_nv;

    const int b   = blockIdx.y;
    const int tid = threadIdx.x;
    const int w   = tid >> 5;
    const int l   = tid & 31;

    // prefetch both global reads up front (latencies overlap)
    const int    v = (mask[(size_t)b * AA + tid] != 0);
    const float2 c = ((const float2*)coords)[(size_t)b * AA + tid];
    {
        unsigned m = __ballot_sync(0xffffffffu, v);
        if (l == 0) svw[w] = m;
    }
    __syncthreads();
    if (tid < 32) {
        int cc = __popc(svw[tid]);
        int x = cc;
#pragma unroll
        for (int o = 1; o < 32; o <<= 1) {
            int y = __shfl_up_sync(0xffffffffu, x, o);
            if (tid >= o) x += y;
        }
        spre[tid] = x - cc;
        if (tid == 31) s_nv = x;
    }
    __syncthreads();
    const int nv = s_nv;

    // scatter valid coords to compacted slots (coords already in regs)
    if (v) {
        int cp = spre[w] + __popc(svw[w] & ((1u << l) - 1));
        scc[cp] = c;
    }
    __syncthreads();

    const int row0 = blockIdx.x * 128;
    if (row0 >= nv) return;
    const int nw = (nv + 31) >> 5;

    const u64* scc64 = (const u64*)scc;
    const int r0 = row0 + (w << 2);   // 4 rows per warp
    bool h[4];
    u64  ci64[4];
#pragma unroll
    for (int r = 0; r < 4; r++) {
        h[r]    = (r0 + r) < nv;
        ci64[r] = scc64[h[r] ? (r0 + r) : 0];
    }
    uint32_t* dst = g_adj + ((size_t)(b * AA) + r0) * 32;

    for (int word = 0; word < nw; word++) {
        // -cj via sign-bit flip: a + (-b) == a - b exactly (IEEE)
        const u64 ncj = scc64[(word << 5) + l] ^ 0x8000000080000000ULL;
        unsigned m[4];
#pragma unroll
        for (int r = 0; r < 4; r++) {
            u64 dp, sq;
            asm("add.rn.f32x2 %0, %1, %2;" : "=l"(dp) : "l"(ci64[r]), "l"(ncj));
            asm("mul.rn.f32x2 %0, %1, %2;" : "=l"(sq) : "l"(dp), "l"(dp));
            float lo = __uint_as_float((unsigned)sq);
            float hi = __uint_as_float((unsigned)(sq >> 32));
            m[r] = __ballot_sync(0xffffffffu, (lo + hi) < THR2);
        }
        if (l == 0) {
#pragma unroll
            for (int r = 0; r < 4; r++)
                if (h[r]) dst[(size_t)r * 32 + word] = m[r];
        }
    }
}

// ---------------------------------------------------------------------------
// Kernel 2: parallel wavefront clustering (32 blocks x 1024 threads).
// R12 core + two conflict fixes:
//  (a) adjacency rows padded to 33 words in SMEM -> adj[tid*33+k] has bank
//      (tid+k)%32, lane-consecutive => conflict-free (was 32-way conflicted
//      in wm precompute, every wavefront round, and the asg post-pass).
//  (b) member masks via one atomicOr per thread into transposed sMembT[w][g]
//      (spread smem atomics) instead of an ng-iteration ballot loop; counts
//      from conflict-free popc sums. g_members global eliminated.
// ---------------------------------------------------------------------------
__global__ __launch_bounds__(1024, 1)
void scan_kernel(const int* __restrict__ mask,
                 float* __restrict__ out_mask,   // may be null
                 float* __restrict__ out_a2g)    // may be null
{
    extern __shared__ unsigned char sraw[];
    uint32_t* adj    = (uint32_t*)sraw;             // AA*33 (padded rows)
    int*      s_cnt  = (int*)(adj + AA * 33);       // AA
    int*      s_goff = s_cnt + AA;                  // AA
    uint32_t* svw    = (uint32_t*)(s_goff + AA);    // 32
    uint32_t* sS     = svw + 32;                    // 32 starter bits (compacted)
    uint32_t* sR     = sS + 32;                     // 32 resolved bits (compacted)
    int*      spre   = (int*)(sR + 32);             // 33 valid prefix
    int*      sSp    = spre + 33;                   // 33 starter prefix
    int*      s_wtot = sSp + 33;                    // 32 warp totals
    __shared__ int s_nres, s_nv, s_ng;

    const int b   = blockIdx.x;
    const int tid = threadIdx.x;
    const int w   = tid >> 5;
    const int l   = tid & 31;

    const int v = (mask[(size_t)b * AA + tid] != 0);
    {
        unsigned m = __ballot_sync(0xffffffffu, v);
        if (l == 0) svw[w] = m;
    }
    if (tid == 0) s_nres = 0;
    __syncthreads();
    if (tid < 32) {
        int c = __popc(svw[tid]);
        int x = c;
#pragma unroll
        for (int o = 1; o < 32; o <<= 1) {
            int y = __shfl_up_sync(0xffffffffu, x, o);
            if (tid >= o) x += y;
        }
        spre[tid] = x - c;
        if (tid == 31) s_nv = x;
        sS[tid] = 0;
    }
    __syncthreads();
    const int nv = s_nv;

    if (tid < 32) {   // resolved-init: nonexistent compacted slots are resolved
        int rem = nv - (tid << 5);
        unsigned occ = rem >= 32 ? 0xffffffffu : (rem > 0 ? ((1u << rem) - 1) : 0u);
        sR[tid] = ~occ;
    }
    // bulk load compacted adjacency rows [0, nv) into PADDED layout (33/row)
    {
        const uint4* src = (const uint4*)(g_adj + (size_t)b * AA * 32);
        const int tot = nv * 8;
        for (int i = tid; i < tot; i += 1024) {
            uint4 v4 = src[i];
            uint32_t* d = adj + (i >> 3) * 33 + ((i & 7) << 2);
            d[0] = v4.x; d[1] = v4.y; d[2] = v4.z; d[3] = v4.w;
        }
    }
    __syncthreads();

    // ---- wavefront: thread tid = compacted agent tid (if < nv) ----
    const bool active = (tid < nv);
    const unsigned ebits = (1u << l) - 1;
    unsigned wm = 0;                       // words with earlier neighbors
    if (active) {
        for (int k = 0; k <= w; k++) {
            unsigned a = adj[tid * 33 + k];
            if (k == w) a &= ebits;
            if (a) wm |= 1u << k;
        }
    }
    bool resolved = !active;
    while (true) {
        bool decR = false, decS = false;
        if (!resolved) {
            bool blocked = false, pend = false;
            unsigned t = wm;
            while (t) {
                int k = __ffs(t) - 1;
                t &= t - 1u;
                unsigned a = adj[tid * 33 + k];
                if (k == w) a &= ebits;
                if (a & sS[k]) { blocked = true; break; }
                if (a & ~sR[k]) pend = true;
            }
            if (blocked)      decR = true;
            else if (!pend) { decS = true; decR = true; }
        }
        __syncthreads();   // snapshot reads complete
        unsigned smw = __ballot_sync(0xffffffffu, decS);
        unsigned rmw = __ballot_sync(0xffffffffu, decR);
        if (l == 0 && smw) sS[w] |= smw;
        if (l == 0 && rmw) { sR[w] |= rmw; atomicAdd(&s_nres, __popc(rmw)); }
        if (decR) resolved = true;
        __syncthreads();   // writes visible
        if (s_nres >= nv) break;
    }

    // starter prefix (rank -> group id)
    if (tid < 32) {
        int c = __popc(sS[tid]);
        int x = c;
#pragma unroll
        for (int o = 1; o < 32; o <<= 1) {
            int y = __shfl_up_sync(0xffffffffu, x, o);
            if (tid >= o) x += y;
        }
        sSp[tid] = x - c;
        if (tid == 31) s_ng = x;
    }
    __syncthreads();

    // asg for ORIGINAL agents: rank of first starter in (compacted row & S)
    int asg = -1;
    if (v) {
        int cp = spre[w] + __popc(svw[w] & ebits);
        int cw = cp >> 5;
        for (int k = 0; k <= cw; k++) {
            unsigned m2 = adj[cp * 33 + k] & sS[k];
            if (m2) {
                int bit = __ffs(m2) - 1;
                asg = sSp[k] + __popc(sS[k] & ((1u << bit) - 1));
                break;
            }
        }
    }
    const int ng = s_ng;

    // ---- member masks via atomicOr into transposed table in dead adj smem --
    __syncthreads();                 // all adj reads done; reuse region
    uint32_t* sMembT = (uint32_t*)sraw;   // [32][1024]: sMembT[w*1024+g]
#pragma unroll
    for (int k = 0; k < 32; k++) sMembT[k * 1024 + tid] = 0;   // conflict-free
    __syncthreads();
    if (v) atomicOr(&sMembT[w * 1024 + asg], 1u << l);         // spread addrs
    __syncthreads();

    // counts: thread tid = group tid (zero for non-groups); conflict-free
    {
        int cnt = 0;
#pragma unroll
        for (int k = 0; k < 32; k++) cnt += __popc(sMembT[k * 1024 + tid]);
        s_cnt[tid] = cnt;
    }
    __syncthreads();

    // ---- exclusive prefix of counts -> s_goff ----
    {
        int val = s_cnt[tid];
        int x = val;
#pragma unroll
        for (int o = 1; o < 32; o <<= 1) {
            int y = __shfl_up_sync(0xffffffffu, x, o);
            if (l >= o) x += y;
        }
        if (l == 31) s_wtot[w] = x;
        __syncthreads();
        if (tid < 32) {
            int c = s_wtot[tid];
            int y = c;
#pragma unroll
            for (int o = 1; o < 32; o <<= 1) {
                int z = __shfl_up_sync(0xffffffffu, y, o);
                if (tid >= o) y += z;
            }
            s_wtot[tid] = y - c;    // exclusive warp offsets
        }
        __syncthreads();
        s_goff[tid] = x - val + s_wtot[w];
    }
    __syncthreads();

    // ---- counting-sorted member list (ascending agent order per group) ----
    if (v) {
        int rank = __popc(sMembT[w * 1024 + asg] & ebits);
        for (int ww = 0; ww < w; ww++) rank += __popc(sMembT[ww * 1024 + asg]);
        g_memlist[b * AA + s_goff[asg] + rank] = tid;
    }

    // emit
    g_cnt[(size_t)b * AA + tid]  = s_cnt[tid];
    g_goff[(size_t)b * AA + tid] = s_goff[tid];
    if (out_a2g)  out_a2g[(size_t)b * AA + tid]  = (float)asg;
    if (out_mask) out_mask[(size_t)b * AA + tid] = (tid < ng) ? 1.0f : 0.0f;
    if (tid == 0) g_ng[b] = ng;
}

// ---------------------------------------------------------------------------
// Kernel 3: fused fill + sparse MLP. [R12 winner — unchanged]
// ---------------------------------------------------------------------------
__global__ __launch_bounds__(512, 1)
void mlp_fill_kernel(const float* __restrict__ emb,
                     const float* __restrict__ W1, const float* __restrict__ b1,
                     const float* __restrict__ W2, const float* __restrict__ b2,
                     float* __restrict__ out)
{
    extern __shared__ float sm[];
    float* sW1T = sm;                  // 16384 floats (4096 float4 slots)
    float* sW2T = sm + 16384;          // 16384
    float* sx   = sm + 32768;          // TMR*DD = 8192
    float* gb1s = sm + 40960;          // 128
    int*   srid = (int*)(sm + 41088);  // 64
    int*   scnt = (int*)(sm + 41152);  // 64

    const int tid  = threadIdx.x;
    const int win  = blockIdx.x;
    const int bb   = win >> 4;              // 16 windows per batch
    const int k0   = (win & 15) * TMR;
    const int ng   = g_ng[bb];
    int live = ng - k0;
    if (live > TMR) live = TMR;
    const bool do_mma = (live > 0);
    const int base = win * TMR;             // == bb*AA + k0

    if (tid < DD) gb1s[tid] = gelu_exact(b1[tid]);
    if (tid < TMR) {
        scnt[tid] = g_cnt[base + tid];
        int rc = tid;
        if (rc > live - 1) rc = live - 1;
        if (rc < 0) rc = 0;
        srid[tid] = base + rc;
    }

    // stage transposed + swizzled weights: slot(c,g) = c*32 + (g ^ ((c>>2)&7))
    // thread mapping c = 4*(i%32) + ((i>>5)&3): conflict-free STS.128.
    if (do_mma) {
        float4* w1t = (float4*)sW1T;
        float4* w2t = (float4*)sW2T;
#pragma unroll
        for (int it = 0; it < 8; it++) {
            int i = tid + it * 512;
            int c = ((i & 31) << 2) | ((i >> 5) & 3);
            int g = i >> 7;
            int slot = c * 32 + (g ^ ((c >> 2) & 7));
            float4 v1, v2;
            v1.x = W1[(4 * g + 0) * DD + c];
            v1.y = W1[(4 * g + 1) * DD + c];
            v1.z = W1[(4 * g + 2) * DD + c];
            v1.w = W1[(4 * g + 3) * DD + c];
            v2.x = W2[(4 * g + 0) * DD + c];
            v2.y = W2[(4 * g + 1) * DD + c];
            v2.z = W2[(4 * g + 2) * DD + c];
            v2.w = W2[(4 * g + 3) * DD + c];
            w1t[slot] = v1;
            w2t[slot] = v2;
        }
    }
    __syncthreads();

    // FILL: constant row for empty groups in this block's window
    if (tid < DD) {
        float a0 = b2[tid], a1 = 0.f, a2 = 0.f, a3 = 0.f;
#pragma unroll 4
        for (int k = 0; k < DD; k += 4) {
            a0 = fmaf(gb1s[k + 0], W2[(k + 0) * DD + tid], a0);
            a1 = fmaf(gb1s[k + 1], W2[(k + 1) * DD + tid], a1);
            a2 = fmaf(gb1s[k + 2], W2[(k + 2) * DD + tid], a2);
            a3 = fmaf(gb1s[k + 3], W2[(k + 3) * DD + tid], a3);
        }
        float cf = (a0 + a1) + (a2 + a3);
        for (int r = 0; r < TMR; r++)
            if (scnt[r] == 0) out[(size_t)(base + r) * DD + tid] = cf;
    }
    if (!do_mma) return;

    const int wp   = tid >> 5;
    const int lane = tid & 31;
    const int r0   = wp * 4;        // 4 rows per warp (16 warps * 4 = 64)
    const int c0   = lane * 4;      // 4 cols per lane
    const int swl  = lane & 7;

    // stage x rows r0..r0+3: mean over contiguous member list.
    int gr4[4], cnt4[4], off4[4];
#pragma unroll
    for (int rr = 0; rr < 4; rr++) {
        gr4[rr]  = srid[r0 + rr];
        cnt4[rr] = scnt[gr4[rr] - base];
        off4[rr] = g_goff[gr4[rr]];        // 4 independent LDGs (overlap)
    }
    const float* ebase = emb + (size_t)bb * AA * DD;
    const int*   mlb   = g_memlist + (size_t)bb * AA;
#pragma unroll 1
    for (int rr = 0; rr < 4; rr++) {
        const int cnt = cnt4[rr];
        const int* ml = mlb + off4[rr];
        float4 a4 = make_float4(0.f, 0.f, 0.f, 0.f);
        int j = 0;
        for (; j + 4 <= cnt; j += 4) {
            int i0 = ml[j], i1 = ml[j + 1], i2 = ml[j + 2], i3 = ml[j + 3];
            float4 v0 = *((const float4*)(ebase + (size_t)i0 * DD) + lane);
            float4 v1 = *((const float4*)(ebase + (size_t)i1 * DD) + lane);
            float4 v2 = *((const float4*)(ebase + (size_t)i2 * DD) + lane);
            float4 v3 = *((const float4*)(ebase + (size_t)i3 * DD) + lane);
            a4.x += (v0.x + v1.x) + (v2.x + v3.x);
            a4.y += (v0.y + v1.y) + (v2.y + v3.y);
            a4.z += (v0.z + v1.z) + (v2.z + v3.z);
            a4.w += (v0.w + v1.w) + (v2.w + v3.w);
        }
        int rem = cnt - j;
        if (rem > 0) {
            // overreads hit g_memlist pad / other entries: values always in
            // [0, AA), so the row loads are safe; contributions gated.
            int i0 = ml[j], i1 = ml[j + 1], i2 = ml[j + 2];
            float f1 = rem > 1 ? 1.f : 0.f;
            float f2 = rem > 2 ? 1.f : 0.f;
            float4 v0 = *((const float4*)(ebase + (size_t)i0 * DD) + lane);
            float4 v1 = *((const float4*)(ebase + (size_t)i1 * DD) + lane);
            float4 v2 = *((const float4*)(ebase + (size_t)i2 * DD) + lane);
            a4.x += v0.x + f1 * v1.x + f2 * v2.x;
            a4.y += v0.y + f1 * v1.y + f2 * v2.y;
            a4.z += v0.z + f1 * v1.z + f2 * v2.z;
            a4.w += v0.w + f1 * v1.w + f2 * v2.w;
        }
        float inv = 1.0f / (float)(cnt > 1 ? cnt : 1);
        a4.x *= inv; a4.y *= inv; a4.z *= inv; a4.w *= inv;
        *(float4*)&sx[(r0 + rr) * DD + c0] = a4;
    }
    __syncwarp();   // warp owns its rows; x within-warp visible

    u64 acc[4][4];

    // ================= layer 1 =================
#pragma unroll
    for (int r = 0; r < 4; r++)
#pragma unroll
        for (int cc = 0; cc < 4; cc++) acc[r][cc] = 0ull;

    {
        const ulonglong2* wp4 = (const ulonglong2*)sW1T;
#pragma unroll 4
        for (int g = 0; g < 32; g++) {
            const int gs = g ^ swl;
            ulonglong2 wv0 = wp4[(c0 + 0) * 32 + gs];
            ulonglong2 wv1 = wp4[(c0 + 1) * 32 + gs];
            ulonglong2 wv2 = wp4[(c0 + 2) * 32 + gs];
            ulonglong2 wv3 = wp4[(c0 + 3) * 32 + gs];
#pragma unroll
            for (int r = 0; r < 4; r++) {
                ulonglong2 xv = *(const ulonglong2*)(sx + (r0 + r) * DD + 4 * g);
                asm("fma.rn.f32x2 %0, %1, %2, %0;" : "+l"(acc[r][0]) : "l"(xv.x), "l"(wv0.x));
                asm("fma.rn.f32x2 %0, %1, %2, %0;" : "+l"(acc[r][1]) : "l"(xv.x), "l"(wv1.x));
                asm("fma.rn.f32x2 %0, %1, %2, %0;" : "+l"(acc[r][2]) : "l"(xv.x), "l"(wv2.x));
                asm("fma.rn.f32x2 %0, %1, %2, %0;" : "+l"(acc[r][3]) : "l"(xv.x), "l"(wv3.x));
                asm("fma.rn.f32x2 %0, %1, %2, %0;" : "+l"(acc[r][0]) : "l"(xv.y), "l"(wv0.y));
                asm("fma.rn.f32x2 %0, %1, %2, %0;" : "+l"(acc[r][1]) : "l"(xv.y), "l"(wv1.y));
                asm("fma.rn.f32x2 %0, %1, %2, %0;" : "+l"(acc[r][2]) : "l"(xv.y), "l"(wv2.y));
                asm("fma.rn.f32x2 %0, %1, %2, %0;" : "+l"(acc[r][3]) : "l"(xv.y), "l"(wv3.y));
            }
        }
    }
    // epilogue 1: h = gelu(lo+hi + b1); warp owns its rows -> no barrier
    {
        float4 bv = *(const float4*)&b1[c0];
#pragma unroll
        for (int r = 0; r < 4; r++) {
            float4 h;
            h.x = gelu_exact(__uint_as_float((unsigned)acc[r][0]) + __uint_as_float((unsigned)(acc[r][0] >> 32)) + bv.x);
            h.y = gelu_exact(__uint_as_float((unsigned)acc[r][1]) + __uint_as_float((unsigned)(acc[r][1] >> 32)) + bv.y);
            h.z = gelu_exact(__uint_as_float((unsigned)acc[r][2]) + __uint_as_float((unsigned)(acc[r][2] >> 32)) + bv.z);
            h.w = gelu_exact(__uint_as_float((unsigned)acc[r][3]) + __uint_as_float((unsigned)(acc[r][3] >> 32)) + bv.w);
            *(float4*)&sx[(r0 + r) * DD + c0] = h;
        }
    }
    __syncwarp();

    // ================= layer 2 =================
#pragma unroll
    for (int r = 0; r < 4; r++)
#pragma unroll
        for (int cc = 0; cc < 4; cc++) acc[r][cc] = 0ull;

    {
        const ulonglong2* wp4 = (const ulonglong2*)sW2T;
#pragma unroll 4
        for (int g = 0; g < 32; g++) {
            const int gs = g ^ swl;
            ulonglong2 wv0 = wp4[(c0 + 0) * 32 + gs];
            ulonglong2 wv1 = wp4[(c0 + 1) * 32 + gs];
            ulonglong2 wv2 = wp4[(c0 + 2) * 32 + gs];
            ulonglong2 wv3 = wp4[(c0 + 3) * 32 + gs];
#pragma unroll
            for (int r = 0; r < 4; r++) {
                ulonglong2 xv = *(const ulonglong2*)(sx + (r0 + r) * DD + 4 * g);
                asm("fma.rn.f32x2 %0, %1, %2, %0;" : "+l"(acc[r][0]) : "l"(xv.x), "l"(wv0.x));
                asm("fma.rn.f32x2 %0, %1, %2, %0;" : "+l"(acc[r][1]) : "l"(xv.x), "l"(wv1.x));
                asm("fma.rn.f32x2 %0, %1, %2, %0;" : "+l"(acc[r][2]) : "l"(xv.x), "l"(wv2.x));
                asm("fma.rn.f32x2 %0, %1, %2, %0;" : "+l"(acc[r][3]) : "l"(xv.x), "l"(wv3.x));
                asm("fma.rn.f32x2 %0, %1, %2, %0;" : "+l"(acc[r][0]) : "l"(xv.y), "l"(wv0.y));
                asm("fma.rn.f32x2 %0, %1, %2, %0;" : "+l"(acc[r][1]) : "l"(xv.y), "l"(wv1.y));
                asm("fma.rn.f32x2 %0, %1, %2, %0;" : "+l"(acc[r][2]) : "l"(xv.y), "l"(wv2.y));
                asm("fma.rn.f32x2 %0, %1, %2, %0;" : "+l"(acc[r][3]) : "l"(xv.y), "l"(wv3.y));
            }
        }
    }
    // epilogue 2: out = lo+hi + b2, store live rows
    {
        float4 bv = *(const float4*)&b2[c0];
#pragma unroll
        for (int r = 0; r < 4; r++) {
            if (r0 + r < live) {
                int gr = srid[r0 + r];
                float4 ov;
                ov.x = __uint_as_float((unsigned)acc[r][0]) + __uint_as_float((unsigned)(acc[r][0] >> 32)) + bv.x;
                ov.y = __uint_as_float((unsigned)acc[r][1]) + __uint_as_float((unsigned)(acc[r][1] >> 32)) + bv.y;
                ov.z = __uint_as_float((unsigned)acc[r][2]) + __uint_as_float((unsigned)(acc[r][2] >> 32)) + bv.z;
                ov.w = __uint_as_float((unsigned)acc[r][3]) + __uint_as_float((unsigned)(acc[r][3] >> 32)) + bv.w;
                *(float4*)&out[(size_t)gr * DD + c0] = ov;
            }
        }
    }
}

// ---------------------------------------------------------------------------
extern "C" void kernel_launch(void* const* d_in, const int* in_sizes, int n_in,
                              void* d_out, int out_size)
{
    const float* emb    = (const float*)d_in[0];
    const float* coords = (const float*)d_in[1];
    const int*   mask   = (const int*)d_in[2];
    const float* W1     = (const float*)d_in[3];
    const float* b1     = (const float*)d_in[4];
    const float* W2     = (const float*)d_in[5];
    const float* b2     = (const float*)d_in[6];

    float* out = (float*)d_out;
    const int tok_elems = BB * AA * DD;
    float* out_mask = (out_size >= tok_elems + BB * AA)     ? out + tok_elems           : nullptr;
    float* out_a2g  = (out_size >= tok_elems + 2 * BB * AA) ? out + tok_elems + BB * AA : nullptr;

    const int smem_scan = AA * 33 * 4 + 2 * AA * 4 + 3 * 32 * 4 + 2 * 33 * 4 + 32 * 4; // 144,136
    const int smem_mlp  = (16384 + 16384 + TMR * DD + DD) * 4 + 2 * TMR * 4;           // 164,864

    cudaFuncSetAttribute(scan_kernel,
                         cudaFuncAttributeMaxDynamicSharedMemorySize, smem_scan);
    cudaFuncSetAttribute(mlp_fill_kernel,
                         cudaFuncAttributeMaxDynamicSharedMemorySize, smem_mlp);

    adjc_kernel<<<dim3(8, BB), 1024>>>(coords, mask);
    scan_kernel<<<BB, 1024, smem_scan>>>(mask, out_mask, out_a2g);
    mlp_fill_kernel<<<(BB * AA) / TMR, 512, smem_mlp>>>(emb, W1, b1, W2, b2, out);
}